// round 8
// baseline (speedup 1.0000x reference)
#include <cuda_runtime.h>
#include <math.h>
#include <stdint.h>

// Shapes (fixed): B=2, S=2048, E=1024, H=16, D=64
// tf32 hi/lo fragment-image planes (all sizes in floats):
//  g_xA : x as A operand    [mb(32)][kt(32)] blocks of 32KB (hi16K|lo16K)
//  g_OA : attn out as A op  same layout
//  g_W*B: weights as B op   [nb(8)][kt(32)] blocks of 32KB
//  g_KA : K as A operand    [hb(32)][mb(16)][kt(2)] blocks of 32KB
//  g_VSB: V as S-GEMM B op  [hb(32)][kb(32)][kt(2)] blocks of 16KB (hi8K|lo8K), n=key64,k=d32
//  g_VPB: V as PV-GEMM B op [hb(32)][kkt(64)] blocks of 16KB (hi8K|lo8K), n=d64,k=key32
static __device__ float g_xA[8 * 1024 * 1024];
static __device__ float g_OA[8 * 1024 * 1024];
static __device__ float g_WkB[2 * 1024 * 1024];
static __device__ float g_WvB[2 * 1024 * 1024];
static __device__ float g_WoB[2 * 1024 * 1024];
static __device__ float g_KA[8 * 1024 * 1024];
static __device__ float g_VSB[8 * 1024 * 1024];
static __device__ float g_VPB[8 * 1024 * 1024];

__device__ __forceinline__ float fast_exp2(float x) {
    float y;
    asm("ex2.approx.ftz.f32 %0, %1;" : "=f"(y) : "f"(x));
    return y;
}
__device__ __forceinline__ uint32_t tf32_of(float x) {
    uint32_t r;
    asm("cvt.rna.tf32.f32 %0, %1;" : "=r"(r) : "f"(x));
    return r;
}
__device__ __forceinline__ void mma16n8k8(float c[4], const uint32_t a[4],
                                          const uint32_t b[2]) {
    asm volatile(
        "mma.sync.aligned.m16n8k8.row.col.f32.tf32.tf32.f32 "
        "{%0,%1,%2,%3}, {%4,%5,%6,%7}, {%8,%9}, {%0,%1,%2,%3};"
        : "+f"(c[0]), "+f"(c[1]), "+f"(c[2]), "+f"(c[3])
        : "r"(a[0]), "r"(a[1]), "r"(a[2]), "r"(a[3]), "r"(b[0]), "r"(b[1]));
}
__device__ __forceinline__ uint32_t smem_u32(const void* p) {
    uint32_t a;
    asm("{ .reg .u64 t; cvta.to.shared.u64 t, %1; cvt.u32.u64 %0, t; }"
        : "=r"(a) : "l"(p));
    return a;
}

#define SW128(o) ((o) ^ (((o) >> 3) & 0x70))
#define CP16(d, s) \
    asm volatile("cp.async.cg.shared.global [%0], [%1], 16;" ::"r"(d), "l"(s) : "memory")
#define CP_COMMIT() asm volatile("cp.async.commit_group;" ::: "memory")
#define CP_WAIT(n) asm volatile("cp.async.wait_group %0;" ::"n"(n) : "memory")

// A-image byte offset inside a 16KB plane (128 rows x 32 k)
__device__ __forceinline__ uint32_t A_off(int row, int k) {
    uint32_t tile = (uint32_t)(row >> 4);
    uint32_t k8 = (uint32_t)(k >> 3);
    uint32_t lane = (uint32_t)(((row & 7) << 2) | (k & 3));
    uint32_t slot = (uint32_t)((((k >> 2) & 1) << 1) | ((row >> 3) & 1));
    return SW128(((k8 * 8 + tile) << 9) + (lane << 4) + (slot << 2));
}
// B-image byte offset inside a 16KB plane (128 n x 32 k)
__device__ __forceinline__ uint32_t B_off(int n, int k) {
    uint32_t tile = (uint32_t)(n >> 3);
    uint32_t k8 = (uint32_t)(k >> 3);
    uint32_t lane = (uint32_t)(((n & 7) << 2) | (k & 3));
    uint32_t cc = (uint32_t)((k >> 2) & 1);
    return SW128(((k8 * 16 + tile) << 8) + (lane << 3) + (cc << 2));
}
// B-image byte offset inside an 8KB plane (64 n x 32 k)
__device__ __forceinline__ uint32_t B_off64(int n, int k) {
    uint32_t tile = (uint32_t)(n >> 3);
    uint32_t k8 = (uint32_t)(k >> 3);
    uint32_t lane = (uint32_t)(((n & 7) << 2) | (k & 3));
    uint32_t cc = (uint32_t)((k >> 2) & 1);
    return SW128(((k8 * 8 + tile) << 8) + (lane << 3) + (cc << 2));
}

// ---------------------------------------------------------------------------
// Split kernel: fp32 -> tf32 hi/lo fragment images (x -> A, Wk/Wv/Wo -> B).
// ---------------------------------------------------------------------------
__global__ __launch_bounds__(128) void split_kernel(const float* __restrict__ x,
                                                    const float* __restrict__ Wk,
                                                    const float* __restrict__ Wv,
                                                    const float* __restrict__ Wo) {
    const int z = blockIdx.z;
    const int mb = blockIdx.y;
    const int kt = blockIdx.x;
    const float* src;
    float* dst;
    int isA;
    if (z == 0) {
        src = x; dst = g_xA; isA = 1;
    } else {
        if (mb >= 8) return;
        src = (z == 1) ? Wk : (z == 2) ? Wv : Wo;
        dst = (z == 1) ? g_WkB : (z == 2) ? g_WvB : g_WoB;
        isA = 0;
    }
    char* blk = (char*)(dst + ((size_t)(mb * 32 + kt)) * 8192);
    const int tid = threadIdx.x;
#pragma unroll
    for (int e = 0; e < 32; e++) {
        int idx = e * 128 + tid;
        int row = idx >> 5;
        int k = idx & 31;
        float v = src[(size_t)(mb * 128 + row) * 1024 + kt * 32 + k];
        uint32_t hi = tf32_of(v);
        uint32_t lo = tf32_of(v - __uint_as_float(hi));
        uint32_t off = isA ? A_off(row, k) : B_off(row, k);
        *reinterpret_cast<uint32_t*>(blk + off) = hi;
        *reinterpret_cast<uint32_t*>(blk + 16384 + off) = lo;
    }
}

// ---------------------------------------------------------------------------
// Image GEMM: C[m,n] = sum_k A[m,k]*W[n,k] (3xTF32). CTA tile 128x128, K=1024.
// 512 threads, 16 warps = 4(M) x 4(N), warp tile 32x32. 3-stage cp.async.
// MMA issue is PASS-MAJOR: same-accumulator distance = 8 instructions.
// wmode: 0 = plain row-major, 1 = K images, 2 = V images.
// ---------------------------------------------------------------------------
#define GM_SMEM_BYTES (3 * 65536)

__device__ __forceinline__ void wr_K_img(int m, int col, float v) {
    int s = m & 2047;
    int hb = ((m >> 11) << 4) + (col >> 6);
    int d = col & 63;
    char* blk = (char*)g_KA + ((size_t)((hb * 16 + (s >> 7)) * 2 + (d >> 5))) * 32768;
    uint32_t off = A_off(s & 127, d & 31);
    uint32_t hi = tf32_of(v);
    uint32_t lo = tf32_of(v - __uint_as_float(hi));
    *reinterpret_cast<uint32_t*>(blk + off) = hi;
    *reinterpret_cast<uint32_t*>(blk + 16384 + off) = lo;
}
__device__ __forceinline__ void wr_V_img(int m, int col, float v) {
    int s = m & 2047;
    int hb = ((m >> 11) << 4) + (col >> 6);
    int d = col & 63;
    uint32_t hi = tf32_of(v);
    uint32_t lo = tf32_of(v - __uint_as_float(hi));
    {
        char* blk = (char*)g_VSB +
                    ((size_t)((hb * 32 + (s >> 6)) * 2 + (d >> 5))) * 16384;
        uint32_t off = B_off64(s & 63, d & 31);
        *reinterpret_cast<uint32_t*>(blk + off) = hi;
        *reinterpret_cast<uint32_t*>(blk + 8192 + off) = lo;
    }
    {
        char* blk = (char*)g_VPB + ((size_t)(hb * 64 + (s >> 5))) * 16384;
        uint32_t off = B_off64(d, s & 31);
        *reinterpret_cast<uint32_t*>(blk + off) = hi;
        *reinterpret_cast<uint32_t*>(blk + 8192 + off) = lo;
    }
}

__device__ void gemm_img_body(const float* __restrict__ Aimg,
                              const float* __restrict__ Bimg,
                              float* __restrict__ Cout, int wmode) {
    extern __shared__ __align__(1024) char smc[];
    const uint32_t sbase = smem_u32(smc);
    const int tid = threadIdx.x;
    const int lane = tid & 31;
    const int wid = tid >> 5;
    const int warpM = wid & 3;
    const int warpN = wid >> 2;
    const int mb = blockIdx.y;
    const int nb = blockIdx.x;

    float c[2][4][4];
#pragma unroll
    for (int i = 0; i < 2; i++)
#pragma unroll
        for (int j = 0; j < 4; j++)
#pragma unroll
            for (int q = 0; q < 4; q++) c[i][j][q] = 0.0f;

    const char* Abase = (const char*)(Aimg) + (size_t)mb * 32 * 32768;
    const char* Bbase = (const char*)(Bimg) + (size_t)nb * 32 * 32768;

    auto issue = [&](int kt) {
        int st = kt % 3;
        if (tid < 256) {
            uint32_t d = sbase + (uint32_t)(st * 65536) + (uint32_t)tid * 128;
            const char* s = Abase + (size_t)kt * 32768 + tid * 128;
#pragma unroll
            for (int j = 0; j < 8; j++) CP16(d + j * 16, s + j * 16);
        } else {
            uint32_t d = sbase + (uint32_t)(st * 65536 + 32768) +
                         (uint32_t)(tid - 256) * 128;
            const char* s = Bbase + (size_t)kt * 32768 + (tid - 256) * 128;
#pragma unroll
            for (int j = 0; j < 8; j++) CP16(d + j * 16, s + j * 16);
        }
        CP_COMMIT();
    };

    issue(0);
    issue(1);
    for (int kt = 0; kt < 32; kt++) {
        if (kt < 31) CP_WAIT(1); else CP_WAIT(0);
        __syncthreads();
        char* smb = smc + (kt % 3) * 65536;

#pragma unroll
        for (int k8 = 0; k8 < 4; k8++) {
            uint32_t ah[2][4], al[2][4], bh[4][2], bl[4][2];
#pragma unroll
            for (int tm = 0; tm < 2; tm++) {
                uint32_t tile = warpM * 2 + tm;
                uint32_t off = SW128((uint32_t)(k8 * 8 + tile) * 512 + lane * 16);
                uint4 h = *reinterpret_cast<const uint4*>(smb + off);
                ah[tm][0] = h.x; ah[tm][1] = h.y; ah[tm][2] = h.z; ah[tm][3] = h.w;
                uint4 l = *reinterpret_cast<const uint4*>(smb + 16384 + off);
                al[tm][0] = l.x; al[tm][1] = l.y; al[tm][2] = l.z; al[tm][3] = l.w;
            }
#pragma unroll
            for (int tn = 0; tn < 4; tn++) {
                uint32_t tile = warpN * 4 + tn;
                uint32_t off = SW128((uint32_t)(k8 * 16 + tile) * 256 + lane * 8);
                uint2 h = *reinterpret_cast<const uint2*>(smb + 32768 + off);
                bh[tn][0] = h.x; bh[tn][1] = h.y;
                uint2 l = *reinterpret_cast<const uint2*>(smb + 49152 + off);
                bl[tn][0] = l.x; bl[tn][1] = l.y;
            }
            // PASS-MAJOR: same accumulator revisited only every 8 instructions
#pragma unroll
            for (int tm = 0; tm < 2; tm++)
#pragma unroll
                for (int tn = 0; tn < 4; tn++) mma16n8k8(c[tm][tn], ah[tm], bh[tn]);
#pragma unroll
            for (int tm = 0; tm < 2; tm++)
#pragma unroll
                for (int tn = 0; tn < 4; tn++) mma16n8k8(c[tm][tn], ah[tm], bl[tn]);
#pragma unroll
            for (int tm = 0; tm < 2; tm++)
#pragma unroll
                for (int tn = 0; tn < 4; tn++) mma16n8k8(c[tm][tn], al[tm], bh[tn]);
        }
        __syncthreads();
        if (kt < 30) issue(kt + 2);
    }

    const int g = lane >> 2;
    const int t4 = lane & 3;
    const int bm = mb * 128;
    const int bn = nb * 128;
#pragma unroll
    for (int tm = 0; tm < 2; tm++) {
#pragma unroll
        for (int tn = 0; tn < 4; tn++) {
            int row0 = bm + warpM * 32 + tm * 16 + g;
            int col = bn + warpN * 32 + tn * 8 + t4 * 2;
#pragma unroll
            for (int hrow = 0; hrow < 2; hrow++) {
                int m = row0 + hrow * 8;
                float v0 = c[tm][tn][2 * hrow];
                float v1 = c[tm][tn][2 * hrow + 1];
                if (wmode == 1) {
                    wr_K_img(m, col, v0);
                    wr_K_img(m, col + 1, v1);
                } else if (wmode == 2) {
                    wr_V_img(m, col, v0);
                    wr_V_img(m, col + 1, v1);
                } else {
                    *reinterpret_cast<float2*>(Cout + (size_t)m * 1024 + col) =
                        make_float2(v0, v1);
                }
            }
        }
    }
}

__global__ __launch_bounds__(512, 1) void proj_img_kernel() {
    if (blockIdx.z == 0)
        gemm_img_body(g_xA, g_WkB, nullptr, 1);
    else
        gemm_img_body(g_xA, g_WvB, nullptr, 2);
}
__global__ __launch_bounds__(512, 1) void oproj_img_kernel(float* __restrict__ out) {
    gemm_img_body(g_OA, g_WoB, out, 0);
}

// ---------------------------------------------------------------------------
// Tensor-core attention. Per (b,h), q-block of 128 rows (CTA), key-tiles of 64.
//   S = K·V^T (3xTF32), online softmax (base-2, scale folded), O += P_q·V.
// 256 threads = 8 warps; warp w owns rows w*16..w*16+15 (full softmax rows).
// MMA issue is PASS-MAJOR (distance-8 accumulator reuse).
// SMEM: K images 64KB | P image 32KB (tf32 hi) | 2 stages x (VSB 32KB + VPB 32KB)
// ---------------------------------------------------------------------------
#define ATT_K 0
#define ATT_P 65536
#define ATT_STG 98304
#define ATT_SMEM_BYTES (98304 + 2 * 65536)

__global__ __launch_bounds__(256, 1) void attn_mma_kernel() {
    extern __shared__ __align__(1024) char smc[];
    const uint32_t sbase = smem_u32(smc);
    const int tid = threadIdx.x;
    const int lane = tid & 31;
    const int w = tid >> 5;
    const int g = lane >> 2;
    const int t4 = lane & 3;
    const int hb = blockIdx.y;
    const int mb = blockIdx.x;
    const float SC = -32.0f * 1.4426950408889634f;

    const char* KAg = (const char*)g_KA + (size_t)(hb * 16 + mb) * 65536;
    const char* VSBg = (const char*)g_VSB + (size_t)hb * 32 * 32768;
    const char* VPBg = (const char*)g_VPB + (size_t)hb * 64 * 16384;

    auto issue_stage = [&](int i) {
        int st = i & 1;
        if (tid < 128) {
            uint32_t d = sbase + (uint32_t)(ATT_STG + st * 65536) + (uint32_t)tid * 256;
            const char* s = VSBg + (size_t)i * 32768 + tid * 256;
#pragma unroll
            for (int j = 0; j < 16; j++) CP16(d + j * 16, s + j * 16);
        } else {
            uint32_t d = sbase + (uint32_t)(ATT_STG + st * 65536 + 32768) +
                         (uint32_t)(tid - 128) * 256;
            const char* s = VPBg + (size_t)(2 * i) * 16384 + (tid - 128) * 256;
#pragma unroll
            for (int j = 0; j < 16; j++) CP16(d + j * 16, s + j * 16);
        }
        CP_COMMIT();
    };

    // Prologue: K (64KB, joins group 0) + stage0, then stage1
    {
        uint32_t d = sbase + (uint32_t)tid * 256;
        const char* s = KAg + tid * 256;
#pragma unroll
        for (int j = 0; j < 16; j++) CP16(d + j * 16, s + j * 16);
    }
    issue_stage(0);
    issue_stage(1);

    float o[8][4];
#pragma unroll
    for (int tn = 0; tn < 8; tn++)
#pragma unroll
        for (int q = 0; q < 4; q++) o[tn][q] = 0.0f;
    float m0 = -INFINITY, m1 = -INFINITY, l0 = 0.0f, l1 = 0.0f;

    for (int i = 0; i < 32; i++) {
        if (i < 31) CP_WAIT(1); else CP_WAIT(0);
        __syncthreads();
        const uint32_t stg = (uint32_t)(ATT_STG + (i & 1) * 65536);

        // ---- S = K·V^T  (128 rows x 64 keys), 3xTF32, pass-major ----
        float s[8][4];
#pragma unroll
        for (int tn = 0; tn < 8; tn++)
#pragma unroll
            for (int q = 0; q < 4; q++) s[tn][q] = 0.0f;
#pragma unroll
        for (int k8 = 0; k8 < 8; k8++) {
            int kt = k8 >> 2;
            int k8i = k8 & 3;
            uint32_t aoff = (uint32_t)(ATT_K + kt * 32768) +
                            SW128((uint32_t)(k8i * 8 + w) * 512 + lane * 16);
            uint4 h4 = *reinterpret_cast<const uint4*>(smc + aoff);
            uint4 l4 = *reinterpret_cast<const uint4*>(smc + aoff + 16384);
            uint32_t ah[4] = {h4.x, h4.y, h4.z, h4.w};
            uint32_t al[4] = {l4.x, l4.y, l4.z, l4.w};
            uint32_t bh[8][2], bl[8][2];
#pragma unroll
            for (int tn = 0; tn < 8; tn++) {
                uint32_t boff = stg + (uint32_t)(kt * 16384) +
                                SW128((uint32_t)(k8i * 8 + tn) * 256 + lane * 8);
                uint2 bh2 = *reinterpret_cast<const uint2*>(smc + boff);
                uint2 bl2 = *reinterpret_cast<const uint2*>(smc + boff + 8192);
                bh[tn][0] = bh2.x; bh[tn][1] = bh2.y;
                bl[tn][0] = bl2.x; bl[tn][1] = bl2.y;
            }
#pragma unroll
            for (int tn = 0; tn < 8; tn++) mma16n8k8(s[tn], ah, bh[tn]);
#pragma unroll
            for (int tn = 0; tn < 8; tn++) mma16n8k8(s[tn], ah, bl[tn]);
#pragma unroll
            for (int tn = 0; tn < 8; tn++) mma16n8k8(s[tn], al, bh[tn]);
        }

        // ---- softmax over this 64-key tile (rows: w*16+g, w*16+g+8) ----
#pragma unroll
        for (int tn = 0; tn < 8; tn++)
#pragma unroll
            for (int q = 0; q < 4; q++) s[tn][q] *= SC;

        float mx0 = s[0][0], mx1 = s[0][2];
#pragma unroll
        for (int tn = 0; tn < 8; tn++) {
            mx0 = fmaxf(mx0, fmaxf(s[tn][0], s[tn][1]));
            mx1 = fmaxf(mx1, fmaxf(s[tn][2], s[tn][3]));
        }
        mx0 = fmaxf(mx0, __shfl_xor_sync(0xffffffffu, mx0, 1));
        mx0 = fmaxf(mx0, __shfl_xor_sync(0xffffffffu, mx0, 2));
        mx1 = fmaxf(mx1, __shfl_xor_sync(0xffffffffu, mx1, 1));
        mx1 = fmaxf(mx1, __shfl_xor_sync(0xffffffffu, mx1, 2));

        float mn0 = fmaxf(m0, mx0), mn1 = fmaxf(m1, mx1);
        float al0 = fast_exp2(m0 - mn0), al1 = fast_exp2(m1 - mn1);
        m0 = mn0; m1 = mn1;

        float rs0 = 0.0f, rs1 = 0.0f;
        const int r0 = w * 16 + g;
#pragma unroll
        for (int tn = 0; tn < 8; tn++) {
#pragma unroll
            for (int q = 0; q < 4; q++) {
                int key = tn * 8 + t4 * 2 + (q & 1);
                int row = r0 + ((q >> 1) << 3);
                float p = fast_exp2(s[tn][q] - ((q < 2) ? mn0 : mn1));
                uint32_t bits = tf32_of(p);
                float pq = __uint_as_float(bits);
                if (q < 2) rs0 += pq; else rs1 += pq;
                *reinterpret_cast<uint32_t*>(
                    smc + ATT_P + (key >> 5) * 16384 + A_off(row, key & 31)) = bits;
            }
        }
        rs0 += __shfl_xor_sync(0xffffffffu, rs0, 1);
        rs0 += __shfl_xor_sync(0xffffffffu, rs0, 2);
        rs1 += __shfl_xor_sync(0xffffffffu, rs1, 1);
        rs1 += __shfl_xor_sync(0xffffffffu, rs1, 2);
        l0 = l0 * al0 + rs0;
        l1 = l1 * al1 + rs1;
#pragma unroll
        for (int tn = 0; tn < 8; tn++) {
            o[tn][0] *= al0; o[tn][1] *= al0;
            o[tn][2] *= al1; o[tn][3] *= al1;
        }
        __syncwarp();

        // ---- O += P_q · V  (128 rows x 64 d, k = 64 keys), pass-major ----
#pragma unroll
        for (int k8 = 0; k8 < 8; k8++) {
            int kp = k8 >> 2;
            int k8i = k8 & 3;
            uint32_t poff = (uint32_t)(ATT_P + kp * 16384) +
                            SW128((uint32_t)(k8i * 8 + w) * 512 + lane * 16);
            uint4 p4 = *reinterpret_cast<const uint4*>(smc + poff);
            uint32_t pa[4] = {p4.x, p4.y, p4.z, p4.w};
            uint32_t vh[8][2], vl[8][2];
#pragma unroll
            for (int tn = 0; tn < 8; tn++) {
                uint32_t voff = stg + (uint32_t)(32768 + kp * 16384) +
                                SW128((uint32_t)(k8i * 8 + tn) * 256 + lane * 8);
                uint2 vh2 = *reinterpret_cast<const uint2*>(smc + voff);
                uint2 vl2 = *reinterpret_cast<const uint2*>(smc + voff + 8192);
                vh[tn][0] = vh2.x; vh[tn][1] = vh2.y;
                vl[tn][0] = vl2.x; vl[tn][1] = vl2.y;
            }
#pragma unroll
            for (int tn = 0; tn < 8; tn++) mma16n8k8(o[tn], pa, vh[tn]);
#pragma unroll
            for (int tn = 0; tn < 8; tn++) mma16n8k8(o[tn], pa, vl[tn]);
        }
        __syncthreads();
        if (i < 30) issue_stage(i + 2);
    }

    // ---- epilogue: normalize and write g_OA A-images ----
    const int b = hb >> 4;
    const int h = hb & 15;
    const float inv0 = 1.0f / l0, inv1 = 1.0f / l1;
    const int rbase = b * 2048 + mb * 128 + w * 16 + g;
#pragma unroll
    for (int tn = 0; tn < 8; tn++) {
#pragma unroll
        for (int q = 0; q < 4; q++) {
            int d = h * 64 + tn * 8 + t4 * 2 + (q & 1);
            int row = rbase + ((q >> 1) << 3);
            float v = o[tn][q] * ((q < 2) ? inv0 : inv1);
            uint32_t hi = tf32_of(v);
            uint32_t lo = tf32_of(v - __uint_as_float(hi));
            char* blk = (char*)g_OA + (size_t)((row >> 7) * 32 + (d >> 5)) * 32768;
            uint32_t off = A_off(row & 127, d & 31);
            *reinterpret_cast<uint32_t*>(blk + off) = hi;
            *reinterpret_cast<uint32_t*>(blk + 16384 + off) = lo;
        }
    }
}

extern "C" void kernel_launch(void* const* d_in, const int* in_sizes, int n_in,
                              void* d_out, int out_size) {
    const float* x = (const float*)d_in[0];
    // d_in[1] = Wq (dead code in the reference dataflow)
    const float* Wk = (const float*)d_in[2];
    const float* Wv = (const float*)d_in[3];
    const float* Wo = (const float*)d_in[4];
    float* out = (float*)d_out;

    cudaFuncSetAttribute(proj_img_kernel, cudaFuncAttributeMaxDynamicSharedMemorySize,
                         GM_SMEM_BYTES);
    cudaFuncSetAttribute(oproj_img_kernel, cudaFuncAttributeMaxDynamicSharedMemorySize,
                         GM_SMEM_BYTES);
    cudaFuncSetAttribute(attn_mma_kernel, cudaFuncAttributeMaxDynamicSharedMemorySize,
                         ATT_SMEM_BYTES);

    // 1) Pre-split inputs into tf32 hi/lo fragment images
    split_kernel<<<dim3(32, 32, 4), 128>>>(x, Wk, Wv, Wo);

    // 2) K/V projections; epilogue writes K/V attention images directly
    proj_img_kernel<<<dim3(8, 32, 2), 512, GM_SMEM_BYTES>>>();

    // 3) Tensor-core attention, writes g_OA images
    attn_mma_kernel<<<dim3(16, 32), 256, ATT_SMEM_BYTES>>>();

    // 4) Output projection
    oproj_img_kernel<<<dim3(8, 32), 512, GM_SMEM_BYTES>>>(out);
}

// round 9
// speedup vs baseline: 1.0174x; 1.0174x over previous
#include <cuda_runtime.h>
#include <math.h>
#include <stdint.h>

// Shapes (fixed): B=2, S=2048, E=1024, H=16, D=64
// tf32 hi/lo fragment-image planes:
//  g_xA : x as A operand    [mb(32)][kt(32)] blocks of 32KB (hi16K|lo16K)
//  g_OA : attn out as A op  same layout
//  g_W*B: weights as B op   [nb(8)][kt(32)] blocks of 32KB
//  g_KA : K as A operand    [hb(32)][mb(16)][kt(2)] blocks of 32KB
//  g_VSB: V as S-GEMM B op  [hb(32)][kb(32)][kt(2)] blocks of 16KB (hi8K|lo8K)
//  g_VPB: V as PV-GEMM B op [hb(32)][kkt(64)] blocks of 16KB (hi8K|lo8K)
static __device__ float g_xA[8 * 1024 * 1024];
static __device__ float g_OA[8 * 1024 * 1024];
static __device__ float g_WkB[2 * 1024 * 1024];
static __device__ float g_WvB[2 * 1024 * 1024];
static __device__ float g_WoB[2 * 1024 * 1024];
static __device__ float g_KA[8 * 1024 * 1024];
static __device__ float g_VSB[8 * 1024 * 1024];
static __device__ float g_VPB[8 * 1024 * 1024];

__device__ __forceinline__ float fast_exp2(float x) {
    float y;
    asm("ex2.approx.ftz.f32 %0, %1;" : "=f"(y) : "f"(x));
    return y;
}
__device__ __forceinline__ uint32_t tf32_of(float x) {
    uint32_t r;
    asm("cvt.rna.tf32.f32 %0, %1;" : "=r"(r) : "f"(x));
    return r;
}
__device__ __forceinline__ void mma16n8k8(float c[4], const uint32_t a[4],
                                          const uint32_t b[2]) {
    asm volatile(
        "mma.sync.aligned.m16n8k8.row.col.f32.tf32.tf32.f32 "
        "{%0,%1,%2,%3}, {%4,%5,%6,%7}, {%8,%9}, {%0,%1,%2,%3};"
        : "+f"(c[0]), "+f"(c[1]), "+f"(c[2]), "+f"(c[3])
        : "r"(a[0]), "r"(a[1]), "r"(a[2]), "r"(a[3]), "r"(b[0]), "r"(b[1]));
}
__device__ __forceinline__ uint32_t smem_u32(const void* p) {
    uint32_t a;
    asm("{ .reg .u64 t; cvta.to.shared.u64 t, %1; cvt.u32.u64 %0, t; }"
        : "=r"(a) : "l"(p));
    return a;
}

#define SW128(o) ((o) ^ (((o) >> 3) & 0x70))
#define CP16(d, s) \
    asm volatile("cp.async.cg.shared.global [%0], [%1], 16;" ::"r"(d), "l"(s) : "memory")
#define CP_COMMIT() asm volatile("cp.async.commit_group;" ::: "memory")
#define CP_WAIT(n) asm volatile("cp.async.wait_group %0;" ::"n"(n) : "memory")

// A-image byte offset inside a 16KB plane (128 rows x 32 k)
__device__ __forceinline__ uint32_t A_off(int row, int k) {
    uint32_t tile = (uint32_t)(row >> 4);
    uint32_t k8 = (uint32_t)(k >> 3);
    uint32_t lane = (uint32_t)(((row & 7) << 2) | (k & 3));
    uint32_t slot = (uint32_t)((((k >> 2) & 1) << 1) | ((row >> 3) & 1));
    return SW128(((k8 * 8 + tile) << 9) + (lane << 4) + (slot << 2));
}
// B-image byte offset inside a 16KB plane (128 n x 32 k)
__device__ __forceinline__ uint32_t B_off(int n, int k) {
    uint32_t tile = (uint32_t)(n >> 3);
    uint32_t k8 = (uint32_t)(k >> 3);
    uint32_t lane = (uint32_t)(((n & 7) << 2) | (k & 3));
    uint32_t cc = (uint32_t)((k >> 2) & 1);
    return SW128(((k8 * 16 + tile) << 8) + (lane << 3) + (cc << 2));
}
// B-image byte offset inside an 8KB plane (64 n x 32 k)
__device__ __forceinline__ uint32_t B_off64(int n, int k) {
    uint32_t tile = (uint32_t)(n >> 3);
    uint32_t k8 = (uint32_t)(k >> 3);
    uint32_t lane = (uint32_t)(((n & 7) << 2) | (k & 3));
    uint32_t cc = (uint32_t)((k >> 2) & 1);
    return SW128(((k8 * 8 + tile) << 8) + (lane << 3) + (cc << 2));
}

// ---------------------------------------------------------------------------
// Split kernel: fp32 -> tf32 hi/lo fragment images (x -> A, Wk/Wv/Wo -> B).
// ---------------------------------------------------------------------------
__global__ __launch_bounds__(128) void split_kernel(const float* __restrict__ x,
                                                    const float* __restrict__ Wk,
                                                    const float* __restrict__ Wv,
                                                    const float* __restrict__ Wo) {
    const int z = blockIdx.z;
    const int mb = blockIdx.y;
    const int kt = blockIdx.x;
    const float* src;
    float* dst;
    int isA;
    if (z == 0) {
        src = x; dst = g_xA; isA = 1;
    } else {
        if (mb >= 8) return;
        src = (z == 1) ? Wk : (z == 2) ? Wv : Wo;
        dst = (z == 1) ? g_WkB : (z == 2) ? g_WvB : g_WoB;
        isA = 0;
    }
    char* blk = (char*)(dst + ((size_t)(mb * 32 + kt)) * 8192);
    const int tid = threadIdx.x;
#pragma unroll
    for (int e = 0; e < 32; e++) {
        int idx = e * 128 + tid;
        int row = idx >> 5;
        int k = idx & 31;
        float v = src[(size_t)(mb * 128 + row) * 1024 + kt * 32 + k];
        uint32_t hi = tf32_of(v);
        uint32_t lo = tf32_of(v - __uint_as_float(hi));
        uint32_t off = isA ? A_off(row, k) : B_off(row, k);
        *reinterpret_cast<uint32_t*>(blk + off) = hi;
        *reinterpret_cast<uint32_t*>(blk + 16384 + off) = lo;
    }
}

// ---------------------------------------------------------------------------
// Image GEMM v2: CTA 128x128, K=1024. 256 threads = 8 warps = 4(M) x 2(N),
// warp tile 32x64 (2 tm x 8 tn). 3-stage cp.async, ONE barrier per K-tile,
// fragment double-buffering across k8 steps, pass-major MMA issue.
// ---------------------------------------------------------------------------
#define GM_SMEM_BYTES (3 * 65536)

__device__ __forceinline__ void wr_K_img(int m, int col, float v) {
    int s = m & 2047;
    int hb = ((m >> 11) << 4) + (col >> 6);
    int d = col & 63;
    char* blk = (char*)g_KA + ((size_t)((hb * 16 + (s >> 7)) * 2 + (d >> 5))) * 32768;
    uint32_t off = A_off(s & 127, d & 31);
    uint32_t hi = tf32_of(v);
    uint32_t lo = tf32_of(v - __uint_as_float(hi));
    *reinterpret_cast<uint32_t*>(blk + off) = hi;
    *reinterpret_cast<uint32_t*>(blk + 16384 + off) = lo;
}
__device__ __forceinline__ void wr_V_img(int m, int col, float v) {
    int s = m & 2047;
    int hb = ((m >> 11) << 4) + (col >> 6);
    int d = col & 63;
    uint32_t hi = tf32_of(v);
    uint32_t lo = tf32_of(v - __uint_as_float(hi));
    {
        char* blk = (char*)g_VSB +
                    ((size_t)((hb * 32 + (s >> 6)) * 2 + (d >> 5))) * 16384;
        uint32_t off = B_off64(s & 63, d & 31);
        *reinterpret_cast<uint32_t*>(blk + off) = hi;
        *reinterpret_cast<uint32_t*>(blk + 8192 + off) = lo;
    }
    {
        char* blk = (char*)g_VPB + ((size_t)(hb * 64 + (s >> 5))) * 16384;
        uint32_t off = B_off64(d, s & 31);
        *reinterpret_cast<uint32_t*>(blk + off) = hi;
        *reinterpret_cast<uint32_t*>(blk + 8192 + off) = lo;
    }
}

__device__ void gemm_img_body(const float* __restrict__ Aimg,
                              const float* __restrict__ Bimg,
                              float* __restrict__ Cout, int wmode) {
    extern __shared__ __align__(1024) char smc[];
    const uint32_t sbase = smem_u32(smc);
    const int tid = threadIdx.x;
    const int lane = tid & 31;
    const int wid = tid >> 5;      // 0..7
    const int warpM = wid & 3;     // 4 in M (32 rows each)
    const int warpN = wid >> 2;    // 2 in N (64 cols each)
    const int mb = blockIdx.y;
    const int nb = blockIdx.x;

    float c[2][8][4];
#pragma unroll
    for (int i = 0; i < 2; i++)
#pragma unroll
        for (int j = 0; j < 8; j++)
#pragma unroll
            for (int q = 0; q < 4; q++) c[i][j][q] = 0.0f;

    // frag buffers [buf][...]
    uint32_t ah[2][2][4], al[2][2][4], bh[2][8][2], bl[2][8][2];

    const char* Abase = (const char*)(Aimg) + (size_t)mb * 32 * 32768;
    const char* Bbase = (const char*)(Bimg) + (size_t)nb * 32 * 32768;

    auto issue = [&](int kt) {
        int st = kt % 3;
        if (tid < 128) {
            uint32_t d = sbase + (uint32_t)(st * 65536) + (uint32_t)tid * 256;
            const char* s = Abase + (size_t)kt * 32768 + tid * 256;
#pragma unroll
            for (int j = 0; j < 16; j++) CP16(d + j * 16, s + j * 16);
        } else {
            uint32_t d = sbase + (uint32_t)(st * 65536 + 32768) +
                         (uint32_t)(tid - 128) * 256;
            const char* s = Bbase + (size_t)kt * 32768 + (tid - 128) * 256;
#pragma unroll
            for (int j = 0; j < 16; j++) CP16(d + j * 16, s + j * 16);
        }
        CP_COMMIT();
    };

    auto ldfrag = [&](const char* smb, int k8, int buf) {
#pragma unroll
        for (int tm = 0; tm < 2; tm++) {
            uint32_t off = SW128((uint32_t)(k8 * 8 + warpM * 2 + tm) * 512 + lane * 16);
            uint4 h = *reinterpret_cast<const uint4*>(smb + off);
            ah[buf][tm][0] = h.x; ah[buf][tm][1] = h.y;
            ah[buf][tm][2] = h.z; ah[buf][tm][3] = h.w;
            uint4 l = *reinterpret_cast<const uint4*>(smb + 16384 + off);
            al[buf][tm][0] = l.x; al[buf][tm][1] = l.y;
            al[buf][tm][2] = l.z; al[buf][tm][3] = l.w;
        }
#pragma unroll
        for (int tn = 0; tn < 8; tn++) {
            uint32_t off = SW128((uint32_t)(k8 * 16 + warpN * 8 + tn) * 256 + lane * 8);
            uint2 h = *reinterpret_cast<const uint2*>(smb + 32768 + off);
            bh[buf][tn][0] = h.x; bh[buf][tn][1] = h.y;
            uint2 l = *reinterpret_cast<const uint2*>(smb + 49152 + off);
            bl[buf][tn][0] = l.x; bl[buf][tn][1] = l.y;
        }
    };

    issue(0);
    issue(1);
    for (int kt = 0; kt < 32; kt++) {
        if (kt < 31) CP_WAIT(1); else CP_WAIT(0);
        __syncthreads();
        if (kt + 2 < 32) issue(kt + 2);  // stage (kt+2)%3: readers done pre-sync
        const char* smb = smc + (kt % 3) * 65536;

        ldfrag(smb, 0, 0);
#pragma unroll
        for (int k8 = 0; k8 < 4; k8++) {
            const int cur = k8 & 1;
            if (k8 < 3) ldfrag(smb, k8 + 1, cur ^ 1);  // overlaps MMAs below
            // pass-major 48 HMMAs on buffer `cur`
#pragma unroll
            for (int tm = 0; tm < 2; tm++)
#pragma unroll
                for (int tn = 0; tn < 8; tn++)
                    mma16n8k8(c[tm][tn], ah[cur][tm], bh[cur][tn]);
#pragma unroll
            for (int tm = 0; tm < 2; tm++)
#pragma unroll
                for (int tn = 0; tn < 8; tn++)
                    mma16n8k8(c[tm][tn], ah[cur][tm], bl[cur][tn]);
#pragma unroll
            for (int tm = 0; tm < 2; tm++)
#pragma unroll
                for (int tn = 0; tn < 8; tn++)
                    mma16n8k8(c[tm][tn], al[cur][tm], bh[cur][tn]);
        }
    }

    const int g = lane >> 2;
    const int t4 = lane & 3;
    const int bm = mb * 128;
    const int bn = nb * 128;
#pragma unroll
    for (int tm = 0; tm < 2; tm++) {
#pragma unroll
        for (int tn = 0; tn < 8; tn++) {
            int row0 = bm + warpM * 32 + tm * 16 + g;
            int col = bn + warpN * 64 + tn * 8 + t4 * 2;
#pragma unroll
            for (int hrow = 0; hrow < 2; hrow++) {
                int m = row0 + hrow * 8;
                float v0 = c[tm][tn][2 * hrow];
                float v1 = c[tm][tn][2 * hrow + 1];
                if (wmode == 1) {
                    wr_K_img(m, col, v0);
                    wr_K_img(m, col + 1, v1);
                } else if (wmode == 2) {
                    wr_V_img(m, col, v0);
                    wr_V_img(m, col + 1, v1);
                } else {
                    *reinterpret_cast<float2*>(Cout + (size_t)m * 1024 + col) =
                        make_float2(v0, v1);
                }
            }
        }
    }
}

__global__ __launch_bounds__(256, 1) void proj_img_kernel() {
    if (blockIdx.z == 0)
        gemm_img_body(g_xA, g_WkB, nullptr, 1);
    else
        gemm_img_body(g_xA, g_WvB, nullptr, 2);
}
__global__ __launch_bounds__(256, 1) void oproj_img_kernel(float* __restrict__ out) {
    gemm_img_body(g_OA, g_WoB, out, 0);
}

// ---------------------------------------------------------------------------
// Tensor-core attention with fragment double-buffering in S and PV loops.
// Per (b,h), q-block of 128 rows (CTA), key-tiles of 64.
// 256 threads = 8 warps; warp w owns rows w*16..w*16+15.
// SMEM: K images 64KB | P image 32KB | 2 stages x (VSB 32KB + VPB 32KB)
// ---------------------------------------------------------------------------
#define ATT_K 0
#define ATT_P 65536
#define ATT_STG 98304
#define ATT_SMEM_BYTES (98304 + 2 * 65536)

__global__ __launch_bounds__(256, 1) void attn_mma_kernel() {
    extern __shared__ __align__(1024) char smc[];
    const uint32_t sbase = smem_u32(smc);
    const int tid = threadIdx.x;
    const int lane = tid & 31;
    const int w = tid >> 5;
    const int g = lane >> 2;
    const int t4 = lane & 3;
    const int hb = blockIdx.y;
    const int mb = blockIdx.x;
    const float SC = -32.0f * 1.4426950408889634f;

    const char* KAg = (const char*)g_KA + (size_t)(hb * 16 + mb) * 65536;
    const char* VSBg = (const char*)g_VSB + (size_t)hb * 32 * 32768;
    const char* VPBg = (const char*)g_VPB + (size_t)hb * 64 * 16384;

    auto issue_stage = [&](int i) {
        int st = i & 1;
        if (tid < 128) {
            uint32_t d = sbase + (uint32_t)(ATT_STG + st * 65536) + (uint32_t)tid * 256;
            const char* s = VSBg + (size_t)i * 32768 + tid * 256;
#pragma unroll
            for (int j = 0; j < 16; j++) CP16(d + j * 16, s + j * 16);
        } else {
            uint32_t d = sbase + (uint32_t)(ATT_STG + st * 65536 + 32768) +
                         (uint32_t)(tid - 128) * 256;
            const char* s = VPBg + (size_t)(2 * i) * 16384 + (tid - 128) * 256;
#pragma unroll
            for (int j = 0; j < 16; j++) CP16(d + j * 16, s + j * 16);
        }
        CP_COMMIT();
    };

    // Prologue: K (64KB, joins group 0) + stage0, then stage1
    {
        uint32_t d = sbase + (uint32_t)tid * 256;
        const char* s = KAg + tid * 256;
#pragma unroll
        for (int j = 0; j < 16; j++) CP16(d + j * 16, s + j * 16);
    }
    issue_stage(0);
    issue_stage(1);

    float o[8][4];
#pragma unroll
    for (int tn = 0; tn < 8; tn++)
#pragma unroll
        for (int q = 0; q < 4; q++) o[tn][q] = 0.0f;
    float m0 = -INFINITY, m1 = -INFINITY, l0 = 0.0f, l1 = 0.0f;

    for (int i = 0; i < 32; i++) {
        if (i < 31) CP_WAIT(1); else CP_WAIT(0);
        __syncthreads();
        const uint32_t stg = (uint32_t)(ATT_STG + (i & 1) * 65536);

        // ---- S = K·V^T (128 x 64), 3xTF32, frag double-buffer, pass-major ----
        float s[8][4];
#pragma unroll
        for (int tn = 0; tn < 8; tn++)
#pragma unroll
            for (int q = 0; q < 4; q++) s[tn][q] = 0.0f;

        uint32_t ah[2][4], al[2][4], bh[2][8][2], bl[2][8][2];
        auto ld_s_frag = [&](int k8, int buf) {
            int kt = k8 >> 2;
            int k8i = k8 & 3;
            uint32_t aoff = (uint32_t)(ATT_K + kt * 32768) +
                            SW128((uint32_t)(k8i * 8 + w) * 512 + lane * 16);
            uint4 h4 = *reinterpret_cast<const uint4*>(smc + aoff);
            uint4 l4 = *reinterpret_cast<const uint4*>(smc + aoff + 16384);
            ah[buf][0] = h4.x; ah[buf][1] = h4.y; ah[buf][2] = h4.z; ah[buf][3] = h4.w;
            al[buf][0] = l4.x; al[buf][1] = l4.y; al[buf][2] = l4.z; al[buf][3] = l4.w;
#pragma unroll
            for (int tn = 0; tn < 8; tn++) {
                uint32_t boff = stg + (uint32_t)(kt * 16384) +
                                SW128((uint32_t)(k8i * 8 + tn) * 256 + lane * 8);
                uint2 bh2 = *reinterpret_cast<const uint2*>(smc + boff);
                uint2 bl2 = *reinterpret_cast<const uint2*>(smc + boff + 8192);
                bh[buf][tn][0] = bh2.x; bh[buf][tn][1] = bh2.y;
                bl[buf][tn][0] = bl2.x; bl[buf][tn][1] = bl2.y;
            }
        };

        ld_s_frag(0, 0);
#pragma unroll
        for (int k8 = 0; k8 < 8; k8++) {
            const int cur = k8 & 1;
            if (k8 < 7) ld_s_frag(k8 + 1, cur ^ 1);
#pragma unroll
            for (int tn = 0; tn < 8; tn++) mma16n8k8(s[tn], ah[cur], bh[cur][tn]);
#pragma unroll
            for (int tn = 0; tn < 8; tn++) mma16n8k8(s[tn], ah[cur], bl[cur][tn]);
#pragma unroll
            for (int tn = 0; tn < 8; tn++) mma16n8k8(s[tn], al[cur], bh[cur][tn]);
        }

        // ---- softmax over this 64-key tile (rows: w*16+g, w*16+g+8) ----
#pragma unroll
        for (int tn = 0; tn < 8; tn++)
#pragma unroll
            for (int q = 0; q < 4; q++) s[tn][q] *= SC;

        float mx0 = s[0][0], mx1 = s[0][2];
#pragma unroll
        for (int tn = 0; tn < 8; tn++) {
            mx0 = fmaxf(mx0, fmaxf(s[tn][0], s[tn][1]));
            mx1 = fmaxf(mx1, fmaxf(s[tn][2], s[tn][3]));
        }
        mx0 = fmaxf(mx0, __shfl_xor_sync(0xffffffffu, mx0, 1));
        mx0 = fmaxf(mx0, __shfl_xor_sync(0xffffffffu, mx0, 2));
        mx1 = fmaxf(mx1, __shfl_xor_sync(0xffffffffu, mx1, 1));
        mx1 = fmaxf(mx1, __shfl_xor_sync(0xffffffffu, mx1, 2));

        float mn0 = fmaxf(m0, mx0), mn1 = fmaxf(m1, mx1);
        float al0 = fast_exp2(m0 - mn0), al1 = fast_exp2(m1 - mn1);
        m0 = mn0; m1 = mn1;

        float rs0 = 0.0f, rs1 = 0.0f;
        const int r0 = w * 16 + g;
#pragma unroll
        for (int tn = 0; tn < 8; tn++) {
#pragma unroll
            for (int q = 0; q < 4; q++) {
                int key = tn * 8 + t4 * 2 + (q & 1);
                int row = r0 + ((q >> 1) << 3);
                float p = fast_exp2(s[tn][q] - ((q < 2) ? mn0 : mn1));
                uint32_t bits = tf32_of(p);
                float pq = __uint_as_float(bits);
                if (q < 2) rs0 += pq; else rs1 += pq;
                *reinterpret_cast<uint32_t*>(
                    smc + ATT_P + (key >> 5) * 16384 + A_off(row, key & 31)) = bits;
            }
        }
        rs0 += __shfl_xor_sync(0xffffffffu, rs0, 1);
        rs0 += __shfl_xor_sync(0xffffffffu, rs0, 2);
        rs1 += __shfl_xor_sync(0xffffffffu, rs1, 1);
        rs1 += __shfl_xor_sync(0xffffffffu, rs1, 2);
        l0 = l0 * al0 + rs0;
        l1 = l1 * al1 + rs1;
#pragma unroll
        for (int tn = 0; tn < 8; tn++) {
            o[tn][0] *= al0; o[tn][1] *= al0;
            o[tn][2] *= al1; o[tn][3] *= al1;
        }
        __syncwarp();

        // ---- O += P_q · V (128 x 64), frag double-buffer, pass-major ----
        uint32_t pa[2][4], vh[2][8][2], vl[2][8][2];
        auto ld_pv_frag = [&](int k8, int buf) {
            int kp = k8 >> 2;
            int k8i = k8 & 3;
            uint32_t poff = (uint32_t)(ATT_P + kp * 16384) +
                            SW128((uint32_t)(k8i * 8 + w) * 512 + lane * 16);
            uint4 p4 = *reinterpret_cast<const uint4*>(smc + poff);
            pa[buf][0] = p4.x; pa[buf][1] = p4.y; pa[buf][2] = p4.z; pa[buf][3] = p4.w;
#pragma unroll
            for (int tn = 0; tn < 8; tn++) {
                uint32_t voff = stg + (uint32_t)(32768 + kp * 16384) +
                                SW128((uint32_t)(k8i * 8 + tn) * 256 + lane * 8);
                uint2 vh2 = *reinterpret_cast<const uint2*>(smc + voff);
                uint2 vl2 = *reinterpret_cast<const uint2*>(smc + voff + 8192);
                vh[buf][tn][0] = vh2.x; vh[buf][tn][1] = vh2.y;
                vl[buf][tn][0] = vl2.x; vl[buf][tn][1] = vl2.y;
            }
        };

        ld_pv_frag(0, 0);
#pragma unroll
        for (int k8 = 0; k8 < 8; k8++) {
            const int cur = k8 & 1;
            if (k8 < 7) ld_pv_frag(k8 + 1, cur ^ 1);
#pragma unroll
            for (int tn = 0; tn < 8; tn++) mma16n8k8(o[tn], pa[cur], vh[cur][tn]);
#pragma unroll
            for (int tn = 0; tn < 8; tn++) mma16n8k8(o[tn], pa[cur], vl[cur][tn]);
        }
        __syncthreads();
        if (i < 30) issue_stage(i + 2);
    }

    // ---- epilogue: normalize and write g_OA A-images ----
    const int b = hb >> 4;
    const int h = hb & 15;
    const float inv0 = 1.0f / l0, inv1 = 1.0f / l1;
    const int rbase = b * 2048 + mb * 128 + w * 16 + g;
#pragma unroll
    for (int tn = 0; tn < 8; tn++) {
#pragma unroll
        for (int q = 0; q < 4; q++) {
            int d = h * 64 + tn * 8 + t4 * 2 + (q & 1);
            int row = rbase + ((q >> 1) << 3);
            float v = o[tn][q] * ((q < 2) ? inv0 : inv1);
            uint32_t hi = tf32_of(v);
            uint32_t lo = tf32_of(v - __uint_as_float(hi));
            char* blk = (char*)g_OA + (size_t)((row >> 7) * 32 + (d >> 5)) * 32768;
            uint32_t off = A_off(row & 127, d & 31);
            *reinterpret_cast<uint32_t*>(blk + off) = hi;
            *reinterpret_cast<uint32_t*>(blk + 16384 + off) = lo;
        }
    }
}

extern "C" void kernel_launch(void* const* d_in, const int* in_sizes, int n_in,
                              void* d_out, int out_size) {
    const float* x = (const float*)d_in[0];
    // d_in[1] = Wq (dead code in the reference dataflow)
    const float* Wk = (const float*)d_in[2];
    const float* Wv = (const float*)d_in[3];
    const float* Wo = (const float*)d_in[4];
    float* out = (float*)d_out;

    cudaFuncSetAttribute(proj_img_kernel, cudaFuncAttributeMaxDynamicSharedMemorySize,
                         GM_SMEM_BYTES);
    cudaFuncSetAttribute(oproj_img_kernel, cudaFuncAttributeMaxDynamicSharedMemorySize,
                         GM_SMEM_BYTES);
    cudaFuncSetAttribute(attn_mma_kernel, cudaFuncAttributeMaxDynamicSharedMemorySize,
                         ATT_SMEM_BYTES);

    // 1) Pre-split inputs into tf32 hi/lo fragment images
    split_kernel<<<dim3(32, 32, 4), 128>>>(x, Wk, Wv, Wo);

    // 2) K/V projections; epilogue writes K/V attention images directly
    proj_img_kernel<<<dim3(8, 32, 2), 256, GM_SMEM_BYTES>>>();

    // 3) Tensor-core attention, writes g_OA images
    attn_mma_kernel<<<dim3(16, 32), 256, ATT_SMEM_BYTES>>>();

    // 4) Output projection
    oproj_img_kernel<<<dim3(8, 32), 256, GM_SMEM_BYTES>>>(out);
}

// round 10
// speedup vs baseline: 1.6255x; 1.5977x over previous
#include <cuda_runtime.h>
#include <math.h>
#include <stdint.h>

// Shapes (fixed): B=2, S=2048, E=1024, H=16, D=64
// bf16 hi/lo fragment-image planes (blocks = hi-plane | lo-plane):
//  g_xA : x as A operand     [mb(32)][kt(32)] blocks of 16KB (hi8K|lo8K)
//  g_OA : attn out as A op   same layout
//  g_W*B: weights as B op    [nb(8)][kt(32)] blocks of 16KB
//  g_KA : K as A operand     [hb(32)][mb(16)][dc(2)] blocks of 16KB
//  g_VSB: V as S-GEMM B op   [hb(32)][kb(32)][dc(2)] blocks of 8KB (hi4K|lo4K)
//  g_VPB: V as PV-GEMM B op  [hb(32)][kkt(64)] blocks of 16KB  (tf32 hi8K|lo8K)
static __device__ float g_xA[8 * 1024 * 1024];
static __device__ float g_OA[8 * 1024 * 1024];
static __device__ float g_WkB[2 * 1024 * 1024];
static __device__ float g_WvB[2 * 1024 * 1024];
static __device__ float g_WoB[2 * 1024 * 1024];
static __device__ float g_KA[8 * 1024 * 1024];
static __device__ float g_VSB[8 * 1024 * 1024];
static __device__ float g_VPB[8 * 1024 * 1024];

__device__ __forceinline__ float fast_exp2(float x) {
    float y;
    asm("ex2.approx.ftz.f32 %0, %1;" : "=f"(y) : "f"(x));
    return y;
}
__device__ __forceinline__ uint32_t tf32_of(float x) {
    uint32_t r;
    asm("cvt.rna.tf32.f32 %0, %1;" : "=r"(r) : "f"(x));
    return r;
}
// pack (v0 -> low half, v1 -> high half) as bf16x2
__device__ __forceinline__ uint32_t bf16x2_pack(float v0, float v1) {
    uint32_t r;
    asm("cvt.rn.bf16x2.f32 %0, %1, %2;" : "=r"(r) : "f"(v1), "f"(v0));
    return r;
}
// split a k-pair into bf16 hi word + bf16 lo (residual) word
__device__ __forceinline__ void bf16_split(float v0, float v1, uint32_t& hw,
                                           uint32_t& lw) {
    hw = bf16x2_pack(v0, v1);
    float h0 = __uint_as_float(hw << 16);
    float h1 = __uint_as_float(hw & 0xFFFF0000u);
    lw = bf16x2_pack(v0 - h0, v1 - h1);
}

__device__ __forceinline__ void mma_bf16(float c[4], const uint32_t a[4],
                                         const uint32_t b[2]) {
    asm volatile(
        "mma.sync.aligned.m16n8k16.row.col.f32.bf16.bf16.f32 "
        "{%0,%1,%2,%3}, {%4,%5,%6,%7}, {%8,%9}, {%0,%1,%2,%3};"
        : "+f"(c[0]), "+f"(c[1]), "+f"(c[2]), "+f"(c[3])
        : "r"(a[0]), "r"(a[1]), "r"(a[2]), "r"(a[3]), "r"(b[0]), "r"(b[1]));
}
__device__ __forceinline__ void mma16n8k8(float c[4], const uint32_t a[4],
                                          const uint32_t b[2]) {
    asm volatile(
        "mma.sync.aligned.m16n8k8.row.col.f32.tf32.tf32.f32 "
        "{%0,%1,%2,%3}, {%4,%5,%6,%7}, {%8,%9}, {%0,%1,%2,%3};"
        : "+f"(c[0]), "+f"(c[1]), "+f"(c[2]), "+f"(c[3])
        : "r"(a[0]), "r"(a[1]), "r"(a[2]), "r"(a[3]), "r"(b[0]), "r"(b[1]));
}
__device__ __forceinline__ uint32_t smem_u32(const void* p) {
    uint32_t a;
    asm("{ .reg .u64 t; cvta.to.shared.u64 t, %1; cvt.u32.u64 %0, t; }"
        : "=r"(a) : "l"(p));
    return a;
}

#define SW128(o) ((o) ^ (((o) >> 3) & 0x70))
#define CP16(d, s) \
    asm volatile("cp.async.cg.shared.global [%0], [%1], 16;" ::"r"(d), "l"(s) : "memory")
#define CP_COMMIT() asm volatile("cp.async.commit_group;" ::: "memory")
#define CP_WAIT(n) asm volatile("cp.async.wait_group %0;" ::"n"(n) : "memory")

// ---- bf16 image word offsets (p = k>>1, pair index 0..15 within 32-k tile) ----
// A-plane 8KB: 128 rows x 32 k
__device__ __forceinline__ uint32_t A16_off(int row, int p) {
    int kc = p >> 3, pi = p & 7;
    uint32_t base = (uint32_t)(kc * 8 + (row >> 4)) << 9;
    uint32_t lane = (uint32_t)(((row & 7) << 2) | (pi & 3));
    uint32_t w = (uint32_t)(((pi >> 2) << 1) | ((row >> 3) & 1));
    return SW128(base + (lane << 4) + (w << 2));
}
// B-plane 8KB: 128 n x 32 k
__device__ __forceinline__ uint32_t B16_off(int n, int p) {
    int kc = p >> 3, pi = p & 7;
    uint32_t base = (uint32_t)(kc * 16 + (n >> 3)) << 8;
    uint32_t lane = (uint32_t)(((n & 7) << 2) | (pi & 3));
    uint32_t w = (uint32_t)(pi >> 2);
    return SW128(base + (lane << 3) + (w << 2));
}
// B-plane 4KB: 64 n x 32 k
__device__ __forceinline__ uint32_t B16_off64(int n, int p) {
    int kc = p >> 3, pi = p & 7;
    uint32_t base = (uint32_t)(kc * 8 + (n >> 3)) << 8;
    uint32_t lane = (uint32_t)(((n & 7) << 2) | (pi & 3));
    uint32_t w = (uint32_t)(pi >> 2);
    return SW128(base + (lane << 3) + (w << 2));
}
// tf32 layouts (P image + VPB only)
__device__ __forceinline__ uint32_t A_off(int row, int k) {
    uint32_t tile = (uint32_t)(row >> 4);
    uint32_t k8 = (uint32_t)(k >> 3);
    uint32_t lane = (uint32_t)(((row & 7) << 2) | (k & 3));
    uint32_t slot = (uint32_t)((((k >> 2) & 1) << 1) | ((row >> 3) & 1));
    return SW128(((k8 * 8 + tile) << 9) + (lane << 4) + (slot << 2));
}
__device__ __forceinline__ uint32_t Btf_off64(int n, int k) {
    uint32_t tile = (uint32_t)(n >> 3);
    uint32_t k8 = (uint32_t)(k >> 3);
    uint32_t lane = (uint32_t)(((n & 7) << 2) | (k & 3));
    uint32_t cc = (uint32_t)((k >> 2) & 1);
    return SW128(((k8 * 8 + tile) << 8) + (lane << 3) + (cc << 2));
}

// ---------------------------------------------------------------------------
// Split kernel: fp32 -> bf16 hi/lo fragment images (x -> A, Wk/Wv/Wo -> B).
// ---------------------------------------------------------------------------
__global__ __launch_bounds__(128) void split_kernel(const float* __restrict__ x,
                                                    const float* __restrict__ Wk,
                                                    const float* __restrict__ Wv,
                                                    const float* __restrict__ Wo) {
    const int z = blockIdx.z;
    const int mb = blockIdx.y;
    const int kt = blockIdx.x;
    const float* src;
    float* dst;
    int isA;
    if (z == 0) {
        src = x; dst = g_xA; isA = 1;
    } else {
        if (mb >= 8) return;
        src = (z == 1) ? Wk : (z == 2) ? Wv : Wo;
        dst = (z == 1) ? g_WkB : (z == 2) ? g_WvB : g_WoB;
        isA = 0;
    }
    char* blk = (char*)dst + (size_t)(mb * 32 + kt) * 16384;
    const int tid = threadIdx.x;
#pragma unroll
    for (int e = 0; e < 16; e++) {
        int idx = e * 128 + tid;
        int row = idx >> 4;
        int p = idx & 15;
        const float* r = src + (size_t)(mb * 128 + row) * 1024 + kt * 32 + p * 2;
        uint32_t hw, lw;
        bf16_split(r[0], r[1], hw, lw);
        uint32_t off = isA ? A16_off(row, p) : B16_off(row, p);
        *reinterpret_cast<uint32_t*>(blk + off) = hw;
        *reinterpret_cast<uint32_t*>(blk + 8192 + off) = lw;
    }
}

// ---------------------------------------------------------------------------
// Image GEMM (3x-bf16 m16n8k16): CTA 128x128, K=1024. 256 threads = 8 warps =
// 4(M) x 2(N), warp tile 32x64. 3-stage cp.async (32KB/stage), one barrier per
// K-tile, fragment double-buffering, pass-major issue.
// Stage: Ahi 8K | Alo 8K | Bhi 8K | Blo 8K.
// wmode: 0 = plain fp32 row-major, 1 = K images, 2 = V images.
// ---------------------------------------------------------------------------
#define GM_SMEM_BYTES (3 * 32768)

__device__ __forceinline__ void wr_K_img(int m, int col, float v0, float v1) {
    int s = m & 2047;
    int hb = ((m >> 11) << 4) + (col >> 6);
    int d = col & 63;
    char* blk = (char*)g_KA +
                (size_t)((hb * 16 + (s >> 7)) * 2 + (d >> 5)) * 16384;
    uint32_t off = A16_off(s & 127, (d & 31) >> 1);
    uint32_t hw, lw;
    bf16_split(v0, v1, hw, lw);
    *reinterpret_cast<uint32_t*>(blk + off) = hw;
    *reinterpret_cast<uint32_t*>(blk + 8192 + off) = lw;
}
__device__ __forceinline__ void wr_V_img(int m, int col, float v0, float v1) {
    int s = m & 2047;
    int hb = ((m >> 11) << 4) + (col >> 6);
    int d = col & 63;
    {   // VSB: bf16, n = key (64), k = d (32)
        char* blk = (char*)g_VSB +
                    (size_t)((hb * 32 + (s >> 6)) * 2 + (d >> 5)) * 8192;
        uint32_t off = B16_off64(s & 63, (d & 31) >> 1);
        uint32_t hw, lw;
        bf16_split(v0, v1, hw, lw);
        *reinterpret_cast<uint32_t*>(blk + off) = hw;
        *reinterpret_cast<uint32_t*>(blk + 4096 + off) = lw;
    }
    {   // VPB: tf32, n = d (64), k = key (32) -- v0/v1 land at adjacent n
        char* blk = (char*)g_VPB + (size_t)(hb * 64 + (s >> 5)) * 16384;
        uint32_t off0 = Btf_off64(d, s & 31);
        uint32_t off1 = Btf_off64(d + 1, s & 31);
        uint32_t h0 = tf32_of(v0), h1 = tf32_of(v1);
        uint32_t l0 = tf32_of(v0 - __uint_as_float(h0));
        uint32_t l1 = tf32_of(v1 - __uint_as_float(h1));
        *reinterpret_cast<uint32_t*>(blk + off0) = h0;
        *reinterpret_cast<uint32_t*>(blk + 8192 + off0) = l0;
        *reinterpret_cast<uint32_t*>(blk + off1) = h1;
        *reinterpret_cast<uint32_t*>(blk + 8192 + off1) = l1;
    }
}

__device__ void gemm_img_body(const float* __restrict__ Aimg,
                              const float* __restrict__ Bimg,
                              float* __restrict__ Cout, int wmode) {
    extern __shared__ __align__(1024) char smc[];
    const uint32_t sbase = smem_u32(smc);
    const int tid = threadIdx.x;
    const int lane = tid & 31;
    const int wid = tid >> 5;
    const int warpM = wid & 3;
    const int warpN = wid >> 2;
    const int mb = blockIdx.y;
    const int nb = blockIdx.x;

    float c[2][8][4];
#pragma unroll
    for (int i = 0; i < 2; i++)
#pragma unroll
        for (int j = 0; j < 8; j++)
#pragma unroll
            for (int q = 0; q < 4; q++) c[i][j][q] = 0.0f;

    uint32_t ah[2][2][4], al[2][2][4], bh[2][8][2], bl[2][8][2];

    const char* Abase = (const char*)(Aimg) + (size_t)mb * 32 * 16384;
    const char* Bbase = (const char*)(Bimg) + (size_t)nb * 32 * 16384;

    auto issue = [&](int kt) {
        int st = kt % 3;
        if (tid < 128) {
            uint32_t d = sbase + (uint32_t)(st * 32768) + (uint32_t)tid * 128;
            const char* s = Abase + (size_t)kt * 16384 + tid * 128;
#pragma unroll
            for (int j = 0; j < 8; j++) CP16(d + j * 16, s + j * 16);
        } else {
            uint32_t d = sbase + (uint32_t)(st * 32768 + 16384) +
                         (uint32_t)(tid - 128) * 128;
            const char* s = Bbase + (size_t)kt * 16384 + (tid - 128) * 128;
#pragma unroll
            for (int j = 0; j < 8; j++) CP16(d + j * 16, s + j * 16);
        }
        CP_COMMIT();
    };

    auto ldfrag = [&](const char* smb, int kc, int buf) {
#pragma unroll
        for (int tm = 0; tm < 2; tm++) {
            uint32_t off = SW128((uint32_t)(kc * 8 + warpM * 2 + tm) * 512 + lane * 16);
            uint4 h = *reinterpret_cast<const uint4*>(smb + off);
            ah[buf][tm][0] = h.x; ah[buf][tm][1] = h.y;
            ah[buf][tm][2] = h.z; ah[buf][tm][3] = h.w;
            uint4 l = *reinterpret_cast<const uint4*>(smb + 8192 + off);
            al[buf][tm][0] = l.x; al[buf][tm][1] = l.y;
            al[buf][tm][2] = l.z; al[buf][tm][3] = l.w;
        }
#pragma unroll
        for (int tn = 0; tn < 8; tn++) {
            uint32_t off = SW128((uint32_t)(kc * 16 + warpN * 8 + tn) * 256 + lane * 8);
            uint2 h = *reinterpret_cast<const uint2*>(smb + 16384 + off);
            bh[buf][tn][0] = h.x; bh[buf][tn][1] = h.y;
            uint2 l = *reinterpret_cast<const uint2*>(smb + 24576 + off);
            bl[buf][tn][0] = l.x; bl[buf][tn][1] = l.y;
        }
    };

    issue(0);
    issue(1);
    for (int kt = 0; kt < 32; kt++) {
        if (kt < 31) CP_WAIT(1); else CP_WAIT(0);
        __syncthreads();
        if (kt + 2 < 32) issue(kt + 2);
        const char* smb = smc + (kt % 3) * 32768;

        ldfrag(smb, 0, 0);
#pragma unroll
        for (int kc = 0; kc < 2; kc++) {
            const int cur = kc & 1;
            if (kc < 1) ldfrag(smb, kc + 1, cur ^ 1);
#pragma unroll
            for (int tm = 0; tm < 2; tm++)
#pragma unroll
                for (int tn = 0; tn < 8; tn++)
                    mma_bf16(c[tm][tn], ah[cur][tm], bh[cur][tn]);
#pragma unroll
            for (int tm = 0; tm < 2; tm++)
#pragma unroll
                for (int tn = 0; tn < 8; tn++)
                    mma_bf16(c[tm][tn], ah[cur][tm], bl[cur][tn]);
#pragma unroll
            for (int tm = 0; tm < 2; tm++)
#pragma unroll
                for (int tn = 0; tn < 8; tn++)
                    mma_bf16(c[tm][tn], al[cur][tm], bh[cur][tn]);
        }
    }

    const int g = lane >> 2;
    const int t4 = lane & 3;
    const int bm = mb * 128;
    const int bn = nb * 128;
#pragma unroll
    for (int tm = 0; tm < 2; tm++) {
#pragma unroll
        for (int tn = 0; tn < 8; tn++) {
            int row0 = bm + warpM * 32 + tm * 16 + g;
            int col = bn + warpN * 64 + tn * 8 + t4 * 2;
#pragma unroll
            for (int hrow = 0; hrow < 2; hrow++) {
                int m = row0 + hrow * 8;
                float v0 = c[tm][tn][2 * hrow];
                float v1 = c[tm][tn][2 * hrow + 1];
                if (wmode == 1) {
                    wr_K_img(m, col, v0, v1);
                } else if (wmode == 2) {
                    wr_V_img(m, col, v0, v1);
                } else {
                    *reinterpret_cast<float2*>(Cout + (size_t)m * 1024 + col) =
                        make_float2(v0, v1);
                }
            }
        }
    }
}

__global__ __launch_bounds__(256, 1) void proj_img_kernel() {
    if (blockIdx.z == 0)
        gemm_img_body(g_xA, g_WkB, nullptr, 1);
    else
        gemm_img_body(g_xA, g_WvB, nullptr, 2);
}
__global__ __launch_bounds__(256, 1) void oproj_img_kernel(float* __restrict__ out) {
    gemm_img_body(g_OA, g_WoB, out, 0);
}

// ---------------------------------------------------------------------------
// Tensor-core attention. S = K·V^T in 3x-bf16 (k16); softmax; O += P·V with P
// in tf32 (2-pass tf32, common-mode P quantization absorbed by l-sum).
// Per (b,h), q-block of 128 rows (CTA), key-tiles of 64. 256 thr = 8 warps.
// SMEM: K bf16 images 32KB | P tf32 image 32KB | 2 stages x (VSB 16KB + VPB 32KB)
// ---------------------------------------------------------------------------
#define ATT_K 0
#define ATT_P 32768
#define ATT_STG 65536
#define ATT_STAGE_SZ 49152
#define ATT_SMEM_BYTES (65536 + 2 * ATT_STAGE_SZ)

__global__ __launch_bounds__(256, 1) void attn_mma_kernel() {
    extern __shared__ __align__(1024) char smc[];
    const uint32_t sbase = smem_u32(smc);
    const int tid = threadIdx.x;
    const int lane = tid & 31;
    const int w = tid >> 5;
    const int g = lane >> 2;
    const int t4 = lane & 3;
    const int hb = blockIdx.y;
    const int mb = blockIdx.x;
    const float SC = -32.0f * 1.4426950408889634f;

    const char* KAg = (const char*)g_KA + (size_t)(hb * 16 + mb) * 32768;
    const char* VSBg = (const char*)g_VSB + (size_t)hb * 32 * 16384;
    const char* VPBg = (const char*)g_VPB + (size_t)hb * 64 * 16384;

    auto issue_stage = [&](int i) {
        uint32_t stg = (uint32_t)(ATT_STG + (i & 1) * ATT_STAGE_SZ);
        if (tid < 128) {
            uint32_t d = sbase + stg + (uint32_t)tid * 128;
            const char* s = VSBg + (size_t)i * 16384 + tid * 128;
#pragma unroll
            for (int j = 0; j < 8; j++) CP16(d + j * 16, s + j * 16);
        } else {
            uint32_t d = sbase + stg + 16384 + (uint32_t)(tid - 128) * 256;
            const char* s = VPBg + (size_t)(2 * i) * 16384 + (tid - 128) * 256;
#pragma unroll
            for (int j = 0; j < 16; j++) CP16(d + j * 16, s + j * 16);
        }
        CP_COMMIT();
    };

    // Prologue: K (32KB, joins group 0) + stage0, then stage1
    {
        uint32_t d = sbase + (uint32_t)tid * 128;
        const char* s = KAg + tid * 128;
#pragma unroll
        for (int j = 0; j < 8; j++) CP16(d + j * 16, s + j * 16);
    }
    issue_stage(0);
    issue_stage(1);

    float o[8][4];
#pragma unroll
    for (int tn = 0; tn < 8; tn++)
#pragma unroll
        for (int q = 0; q < 4; q++) o[tn][q] = 0.0f;
    float m0 = -INFINITY, m1 = -INFINITY, l0 = 0.0f, l1 = 0.0f;

    for (int i = 0; i < 32; i++) {
        if (i < 31) CP_WAIT(1); else CP_WAIT(0);
        __syncthreads();
        const uint32_t stg = (uint32_t)(ATT_STG + (i & 1) * ATT_STAGE_SZ);

        // ---- S = K·V^T (128 x 64), 3x-bf16, frag double-buffer, pass-major ----
        float s[8][4];
#pragma unroll
        for (int tn = 0; tn < 8; tn++)
#pragma unroll
            for (int q = 0; q < 4; q++) s[tn][q] = 0.0f;

        uint32_t ah[2][4], al[2][4], bh[2][8][2], bl[2][8][2];
        auto ld_s_frag = [&](int kc, int buf) {
            int dc = kc >> 1;   // which 32-d chunk (16KB block)
            int kci = kc & 1;   // k16 chunk within block
            uint32_t aoff = (uint32_t)(ATT_K + dc * 16384) +
                            SW128((uint32_t)(kci * 8 + w) * 512 + lane * 16);
            uint4 h4 = *reinterpret_cast<const uint4*>(smc + aoff);
            uint4 l4 = *reinterpret_cast<const uint4*>(smc + aoff + 8192);
            ah[buf][0] = h4.x; ah[buf][1] = h4.y; ah[buf][2] = h4.z; ah[buf][3] = h4.w;
            al[buf][0] = l4.x; al[buf][1] = l4.y; al[buf][2] = l4.z; al[buf][3] = l4.w;
#pragma unroll
            for (int tn = 0; tn < 8; tn++) {
                uint32_t boff = stg + (uint32_t)(dc * 8192) +
                                SW128((uint32_t)(kci * 8 + tn) * 256 + lane * 8);
                uint2 bh2 = *reinterpret_cast<const uint2*>(smc + boff);
                uint2 bl2 = *reinterpret_cast<const uint2*>(smc + boff + 4096);
                bh[buf][tn][0] = bh2.x; bh[buf][tn][1] = bh2.y;
                bl[buf][tn][0] = bl2.x; bl[buf][tn][1] = bl2.y;
            }
        };

        ld_s_frag(0, 0);
#pragma unroll
        for (int kc = 0; kc < 4; kc++) {
            const int cur = kc & 1;
            if (kc < 3) ld_s_frag(kc + 1, cur ^ 1);
#pragma unroll
            for (int tn = 0; tn < 8; tn++) mma_bf16(s[tn], ah[cur], bh[cur][tn]);
#pragma unroll
            for (int tn = 0; tn < 8; tn++) mma_bf16(s[tn], ah[cur], bl[cur][tn]);
#pragma unroll
            for (int tn = 0; tn < 8; tn++) mma_bf16(s[tn], al[cur], bh[cur][tn]);
        }

        // ---- softmax over this 64-key tile (rows: w*16+g, w*16+g+8) ----
#pragma unroll
        for (int tn = 0; tn < 8; tn++)
#pragma unroll
            for (int q = 0; q < 4; q++) s[tn][q] *= SC;

        float mx0 = s[0][0], mx1 = s[0][2];
#pragma unroll
        for (int tn = 0; tn < 8; tn++) {
            mx0 = fmaxf(mx0, fmaxf(s[tn][0], s[tn][1]));
            mx1 = fmaxf(mx1, fmaxf(s[tn][2], s[tn][3]));
        }
        mx0 = fmaxf(mx0, __shfl_xor_sync(0xffffffffu, mx0, 1));
        mx0 = fmaxf(mx0, __shfl_xor_sync(0xffffffffu, mx0, 2));
        mx1 = fmaxf(mx1, __shfl_xor_sync(0xffffffffu, mx1, 1));
        mx1 = fmaxf(mx1, __shfl_xor_sync(0xffffffffu, mx1, 2));

        float mn0 = fmaxf(m0, mx0), mn1 = fmaxf(m1, mx1);
        float al0 = fast_exp2(m0 - mn0), al1 = fast_exp2(m1 - mn1);
        m0 = mn0; m1 = mn1;

        float rs0 = 0.0f, rs1 = 0.0f;
        const int r0 = w * 16 + g;
#pragma unroll
        for (int tn = 0; tn < 8; tn++) {
#pragma unroll
            for (int q = 0; q < 4; q++) {
                int key = tn * 8 + t4 * 2 + (q & 1);
                int row = r0 + ((q >> 1) << 3);
                float p = fast_exp2(s[tn][q] - ((q < 2) ? mn0 : mn1));
                uint32_t bits = tf32_of(p);
                float pq = __uint_as_float(bits);
                if (q < 2) rs0 += pq; else rs1 += pq;
                *reinterpret_cast<uint32_t*>(
                    smc + ATT_P + (key >> 5) * 16384 + A_off(row, key & 31)) = bits;
            }
        }
        rs0 += __shfl_xor_sync(0xffffffffu, rs0, 1);
        rs0 += __shfl_xor_sync(0xffffffffu, rs0, 2);
        rs1 += __shfl_xor_sync(0xffffffffu, rs1, 1);
        rs1 += __shfl_xor_sync(0xffffffffu, rs1, 2);
        l0 = l0 * al0 + rs0;
        l1 = l1 * al1 + rs1;
#pragma unroll
        for (int tn = 0; tn < 8; tn++) {
            o[tn][0] *= al0; o[tn][1] *= al0;
            o[tn][2] *= al1; o[tn][3] *= al1;
        }
        __syncwarp();

        // ---- O += P_q · V (tf32 2-pass), frag double-buffer ----
        uint32_t pa[2][4], vh[2][8][2], vl[2][8][2];
        auto ld_pv_frag = [&](int k8, int buf) {
            int kp = k8 >> 2;
            int k8i = k8 & 3;
            uint32_t poff = (uint32_t)(ATT_P + kp * 16384) +
                            SW128((uint32_t)(k8i * 8 + w) * 512 + lane * 16);
            uint4 p4 = *reinterpret_cast<const uint4*>(smc + poff);
            pa[buf][0] = p4.x; pa[buf][1] = p4.y; pa[buf][2] = p4.z; pa[buf][3] = p4.w;
#pragma unroll
            for (int tn = 0; tn < 8; tn++) {
                uint32_t voff = stg + (uint32_t)(16384 + kp * 16384) +
                                SW128((uint32_t)(k8i * 8 + tn) * 256 + lane * 8);
                uint2 vh2 = *reinterpret_cast<const uint2*>(smc + voff);
                uint2 vl2 = *reinterpret_cast<const uint2*>(smc + voff + 8192);
                vh[buf][tn][0] = vh2.x; vh[buf][tn][1] = vh2.y;
                vl[buf][tn][0] = vl2.x; vl[buf][tn][1] = vl2.y;
            }
        };

        ld_pv_frag(0, 0);
#pragma unroll
        for (int k8 = 0; k8 < 8; k8++) {
            const int cur = k8 & 1;
            if (k8 < 7) ld_pv_frag(k8 + 1, cur ^ 1);
#pragma unroll
            for (int tn = 0; tn < 8; tn++) mma16n8k8(o[tn], pa[cur], vh[cur][tn]);
#pragma unroll
            for (int tn = 0; tn < 8; tn++) mma16n8k8(o[tn], pa[cur], vl[cur][tn]);
        }
        __syncthreads();
        if (i < 30) issue_stage(i + 2);
    }

    // ---- epilogue: normalize and write g_OA bf16 A-images ----
    const int b = hb >> 4;
    const int h = hb & 15;
    const float inv0 = 1.0f / l0, inv1 = 1.0f / l1;
    const int rbase = b * 2048 + mb * 128 + w * 16 + g;
#pragma unroll
    for (int tn = 0; tn < 8; tn++) {
        int d0 = h * 64 + tn * 8 + t4 * 2;
#pragma unroll
        for (int hrow = 0; hrow < 2; hrow++) {
            int row = rbase + hrow * 8;
            float inv = hrow ? inv1 : inv0;
            float v0 = o[tn][2 * hrow] * inv;
            float v1 = o[tn][2 * hrow + 1] * inv;
            char* blk = (char*)g_OA + (size_t)((row >> 7) * 32 + (d0 >> 5)) * 16384;
            uint32_t off = A16_off(row & 127, (d0 & 31) >> 1);
            uint32_t hw, lw;
            bf16_split(v0, v1, hw, lw);
            *reinterpret_cast<uint32_t*>(blk + off) = hw;
            *reinterpret_cast<uint32_t*>(blk + 8192 + off) = lw;
        }
    }
}

extern "C" void kernel_launch(void* const* d_in, const int* in_sizes, int n_in,
                              void* d_out, int out_size) {
    const float* x = (const float*)d_in[0];
    // d_in[1] = Wq (dead code in the reference dataflow)
    const float* Wk = (const float*)d_in[2];
    const float* Wv = (const float*)d_in[3];
    const float* Wo = (const float*)d_in[4];
    float* out = (float*)d_out;

    cudaFuncSetAttribute(proj_img_kernel, cudaFuncAttributeMaxDynamicSharedMemorySize,
                         GM_SMEM_BYTES);
    cudaFuncSetAttribute(oproj_img_kernel, cudaFuncAttributeMaxDynamicSharedMemorySize,
                         GM_SMEM_BYTES);
    cudaFuncSetAttribute(attn_mma_kernel, cudaFuncAttributeMaxDynamicSharedMemorySize,
                         ATT_SMEM_BYTES);

    // 1) Pre-split inputs into bf16 hi/lo fragment images
    split_kernel<<<dim3(32, 32, 4), 128>>>(x, Wk, Wv, Wo);

    // 2) K/V projections (3x-bf16); epilogues write K/V attention images
    proj_img_kernel<<<dim3(8, 32, 2), 256, GM_SMEM_BYTES>>>();

    // 3) Tensor-core attention (S: 3x-bf16, PV: 2x-tf32), writes g_OA images
    attn_mma_kernel<<<dim3(16, 32), 256, ATT_SMEM_BYTES>>>();

    // 4) Output projection (3x-bf16)
    oproj_img_kernel<<<dim3(8, 32), 256, GM_SMEM_BYTES>>>(out);
}

// round 11
// speedup vs baseline: 1.9002x; 1.1690x over previous
#include <cuda_runtime.h>
#include <math.h>
#include <stdint.h>

// Shapes (fixed): B=2, S=2048, E=1024, H=16, D=64
// bf16 hi/lo fragment-image planes (blocks = hi-plane | lo-plane):
//  g_xA : x as A operand     [mb(32)][kt(32)] blocks of 16KB (hi8K|lo8K)
//  g_OA : attn out as A op   same layout
//  g_W*B: weights as B op    [nb(8)][kt(32)] blocks of 16KB
//  g_KA : K as A operand     [hb(32)][mb(16)][dc(2)] blocks of 16KB
//  g_VSB: V as S-GEMM B op   [hb(32)][kb(32)][dc(2)] blocks of 8KB (hi4K|lo4K), n=key64,k=d32
//  g_VPB: V as PV-GEMM B op  [hb(32)][kc(64)] blocks of 8KB (hi4K|lo4K), n=d64,k=key32
static __device__ float g_xA[8 * 1024 * 1024];
static __device__ float g_OA[8 * 1024 * 1024];
static __device__ float g_WkB[2 * 1024 * 1024];
static __device__ float g_WvB[2 * 1024 * 1024];
static __device__ float g_WoB[2 * 1024 * 1024];
static __device__ float g_KA[8 * 1024 * 1024];
static __device__ float g_VSB[8 * 1024 * 1024];
static __device__ float g_VPB[4 * 1024 * 1024];

__device__ __forceinline__ float fast_exp2(float x) {
    float y;
    asm("ex2.approx.ftz.f32 %0, %1;" : "=f"(y) : "f"(x));
    return y;
}
// pack (v0 -> low half, v1 -> high half) as bf16x2
__device__ __forceinline__ uint32_t bf16x2_pack(float v0, float v1) {
    uint32_t r;
    asm("cvt.rn.bf16x2.f32 %0, %1, %2;" : "=r"(r) : "f"(v1), "f"(v0));
    return r;
}
// split a k-pair into bf16 hi word + bf16 lo (residual) word
__device__ __forceinline__ void bf16_split(float v0, float v1, uint32_t& hw,
                                           uint32_t& lw) {
    hw = bf16x2_pack(v0, v1);
    float h0 = __uint_as_float(hw << 16);
    float h1 = __uint_as_float(hw & 0xFFFF0000u);
    lw = bf16x2_pack(v0 - h0, v1 - h1);
}

__device__ __forceinline__ void mma_bf16(float c[4], const uint32_t a[4],
                                         const uint32_t b[2]) {
    asm volatile(
        "mma.sync.aligned.m16n8k16.row.col.f32.bf16.bf16.f32 "
        "{%0,%1,%2,%3}, {%4,%5,%6,%7}, {%8,%9}, {%0,%1,%2,%3};"
        : "+f"(c[0]), "+f"(c[1]), "+f"(c[2]), "+f"(c[3])
        : "r"(a[0]), "r"(a[1]), "r"(a[2]), "r"(a[3]), "r"(b[0]), "r"(b[1]));
}
__device__ __forceinline__ uint32_t smem_u32(const void* p) {
    uint32_t a;
    asm("{ .reg .u64 t; cvta.to.shared.u64 t, %1; cvt.u32.u64 %0, t; }"
        : "=r"(a) : "l"(p));
    return a;
}

#define SW128(o) ((o) ^ (((o) >> 3) & 0x70))
#define CP16(d, s) \
    asm volatile("cp.async.cg.shared.global [%0], [%1], 16;" ::"r"(d), "l"(s) : "memory")
#define CP_COMMIT() asm volatile("cp.async.commit_group;" ::: "memory")
#define CP_WAIT(n) asm volatile("cp.async.wait_group %0;" ::"n"(n) : "memory")

// ---- bf16 image word offsets (p = k>>1, pair index 0..15 within 32-k tile) ----
// A-plane 8KB: 128 rows x 32 k
__device__ __forceinline__ uint32_t A16_off(int row, int p) {
    int kc = p >> 3, pi = p & 7;
    uint32_t base = (uint32_t)(kc * 8 + (row >> 4)) << 9;
    uint32_t lane = (uint32_t)(((row & 7) << 2) | (pi & 3));
    uint32_t w = (uint32_t)(((pi >> 2) << 1) | ((row >> 3) & 1));
    return SW128(base + (lane << 4) + (w << 2));
}
// B-plane 8KB: 128 n x 32 k
__device__ __forceinline__ uint32_t B16_off(int n, int p) {
    int kc = p >> 3, pi = p & 7;
    uint32_t base = (uint32_t)(kc * 16 + (n >> 3)) << 8;
    uint32_t lane = (uint32_t)(((n & 7) << 2) | (pi & 3));
    uint32_t w = (uint32_t)(pi >> 2);
    return SW128(base + (lane << 3) + (w << 2));
}
// B-plane 4KB: 64 n x 32 k
__device__ __forceinline__ uint32_t B16_off64(int n, int p) {
    int kc = p >> 3, pi = p & 7;
    uint32_t base = (uint32_t)(kc * 8 + (n >> 3)) << 8;
    uint32_t lane = (uint32_t)(((n & 7) << 2) | (pi & 3));
    uint32_t w = (uint32_t)(pi >> 2);
    return SW128(base + (lane << 3) + (w << 2));
}

// ---------------------------------------------------------------------------
// Split kernel: fp32 -> bf16 hi/lo fragment images (x -> A, Wk/Wv/Wo -> B).
// ---------------------------------------------------------------------------
__global__ __launch_bounds__(128) void split_kernel(const float* __restrict__ x,
                                                    const float* __restrict__ Wk,
                                                    const float* __restrict__ Wv,
                                                    const float* __restrict__ Wo) {
    const int z = blockIdx.z;
    const int mb = blockIdx.y;
    const int kt = blockIdx.x;
    const float* src;
    float* dst;
    int isA;
    if (z == 0) {
        src = x; dst = g_xA; isA = 1;
    } else {
        if (mb >= 8) return;
        src = (z == 1) ? Wk : (z == 2) ? Wv : Wo;
        dst = (z == 1) ? g_WkB : (z == 2) ? g_WvB : g_WoB;
        isA = 0;
    }
    char* blk = (char*)dst + (size_t)(mb * 32 + kt) * 16384;
    const int tid = threadIdx.x;
#pragma unroll
    for (int e = 0; e < 16; e++) {
        int idx = e * 128 + tid;
        int row = idx >> 4;
        int p = idx & 15;
        const float* r = src + (size_t)(mb * 128 + row) * 1024 + kt * 32 + p * 2;
        uint32_t hw, lw;
        bf16_split(r[0], r[1], hw, lw);
        uint32_t off = isA ? A16_off(row, p) : B16_off(row, p);
        *reinterpret_cast<uint32_t*>(blk + off) = hw;
        *reinterpret_cast<uint32_t*>(blk + 8192 + off) = lw;
    }
}

// ---------------------------------------------------------------------------
// Image GEMM (3x-bf16 m16n8k16): CTA 128x128, K=1024. 256 threads = 8 warps =
// 4(M) x 2(N), warp tile 32x64. 3-stage cp.async (32KB/stage), one barrier per
// K-tile, fragment double-buffering, pass-major issue.
// Stage: Ahi 8K | Alo 8K | Bhi 8K | Blo 8K.
// wmode: 0 = plain fp32 row-major, 1 = K images, 2 = V images.
// ---------------------------------------------------------------------------
#define GM_SMEM_BYTES (3 * 32768)

__device__ __forceinline__ void wr_K_img(int m, int col, float v0, float v1) {
    int s = m & 2047;
    int hb = ((m >> 11) << 4) + (col >> 6);
    int d = col & 63;
    char* blk = (char*)g_KA +
                (size_t)((hb * 16 + (s >> 7)) * 2 + (d >> 5)) * 16384;
    uint32_t off = A16_off(s & 127, (d & 31) >> 1);
    uint32_t hw, lw;
    bf16_split(v0, v1, hw, lw);
    *reinterpret_cast<uint32_t*>(blk + off) = hw;
    *reinterpret_cast<uint32_t*>(blk + 8192 + off) = lw;
}
__device__ __forceinline__ void wr_V_img(int m, int col, float v0, float v1) {
    int s = m & 2047;
    int hb = ((m >> 11) << 4) + (col >> 6);
    int d = col & 63;
    {   // VSB: bf16, n = key (64), k = d (32)
        char* blk = (char*)g_VSB +
                    (size_t)((hb * 32 + (s >> 6)) * 2 + (d >> 5)) * 8192;
        uint32_t off = B16_off64(s & 63, (d & 31) >> 1);
        uint32_t hw, lw;
        bf16_split(v0, v1, hw, lw);
        *reinterpret_cast<uint32_t*>(blk + off) = hw;
        *reinterpret_cast<uint32_t*>(blk + 4096 + off) = lw;
    }
    {   // VPB: bf16, n = d (64), k = key (32). Adjacent keys live in adjacent
        // g-lanes (lane ^ 4); even-g lanes pack (key s, key s+1) and write.
        float u0 = __shfl_xor_sync(0xffffffffu, v0, 4);
        float u1 = __shfl_xor_sync(0xffffffffu, v1, 4);
        int lane = (int)(threadIdx.x & 31);
        if (!(lane & 4)) {
            char* blk = (char*)g_VPB + (size_t)(hb * 64 + (s >> 5)) * 8192;
            uint32_t p = (uint32_t)((s & 31) >> 1);
            uint32_t off0 = B16_off64(d, p);
            uint32_t off1 = B16_off64(d + 1, p);
            uint32_t hw0, lw0, hw1, lw1;
            bf16_split(v0, u0, hw0, lw0);
            bf16_split(v1, u1, hw1, lw1);
            *reinterpret_cast<uint32_t*>(blk + off0) = hw0;
            *reinterpret_cast<uint32_t*>(blk + 4096 + off0) = lw0;
            *reinterpret_cast<uint32_t*>(blk + off1) = hw1;
            *reinterpret_cast<uint32_t*>(blk + 4096 + off1) = lw1;
        }
    }
}

__device__ void gemm_img_body(const float* __restrict__ Aimg,
                              const float* __restrict__ Bimg,
                              float* __restrict__ Cout, int wmode) {
    extern __shared__ __align__(1024) char smc[];
    const uint32_t sbase = smem_u32(smc);
    const int tid = threadIdx.x;
    const int lane = tid & 31;
    const int wid = tid >> 5;
    const int warpM = wid & 3;
    const int warpN = wid >> 2;
    const int mb = blockIdx.y;
    const int nb = blockIdx.x;

    float c[2][8][4];
#pragma unroll
    for (int i = 0; i < 2; i++)
#pragma unroll
        for (int j = 0; j < 8; j++)
#pragma unroll
            for (int q = 0; q < 4; q++) c[i][j][q] = 0.0f;

    uint32_t ah[2][2][4], al[2][2][4], bh[2][8][2], bl[2][8][2];

    const char* Abase = (const char*)(Aimg) + (size_t)mb * 32 * 16384;
    const char* Bbase = (const char*)(Bimg) + (size_t)nb * 32 * 16384;

    auto issue = [&](int kt) {
        int st = kt % 3;
        if (tid < 128) {
            uint32_t d = sbase + (uint32_t)(st * 32768) + (uint32_t)tid * 128;
            const char* s = Abase + (size_t)kt * 16384 + tid * 128;
#pragma unroll
            for (int j = 0; j < 8; j++) CP16(d + j * 16, s + j * 16);
        } else {
            uint32_t d = sbase + (uint32_t)(st * 32768 + 16384) +
                         (uint32_t)(tid - 128) * 128;
            const char* s = Bbase + (size_t)kt * 16384 + (tid - 128) * 128;
#pragma unroll
            for (int j = 0; j < 8; j++) CP16(d + j * 16, s + j * 16);
        }
        CP_COMMIT();
    };

    auto ldfrag = [&](const char* smb, int kc, int buf) {
#pragma unroll
        for (int tm = 0; tm < 2; tm++) {
            uint32_t off = SW128((uint32_t)(kc * 8 + warpM * 2 + tm) * 512 + lane * 16);
            uint4 h = *reinterpret_cast<const uint4*>(smb + off);
            ah[buf][tm][0] = h.x; ah[buf][tm][1] = h.y;
            ah[buf][tm][2] = h.z; ah[buf][tm][3] = h.w;
            uint4 l = *reinterpret_cast<const uint4*>(smb + 8192 + off);
            al[buf][tm][0] = l.x; al[buf][tm][1] = l.y;
            al[buf][tm][2] = l.z; al[buf][tm][3] = l.w;
        }
#pragma unroll
        for (int tn = 0; tn < 8; tn++) {
            uint32_t off = SW128((uint32_t)(kc * 16 + warpN * 8 + tn) * 256 + lane * 8);
            uint2 h = *reinterpret_cast<const uint2*>(smb + 16384 + off);
            bh[buf][tn][0] = h.x; bh[buf][tn][1] = h.y;
            uint2 l = *reinterpret_cast<const uint2*>(smb + 24576 + off);
            bl[buf][tn][0] = l.x; bl[buf][tn][1] = l.y;
        }
    };

    issue(0);
    issue(1);
    for (int kt = 0; kt < 32; kt++) {
        if (kt < 31) CP_WAIT(1); else CP_WAIT(0);
        __syncthreads();
        if (kt + 2 < 32) issue(kt + 2);
        const char* smb = smc + (kt % 3) * 32768;

        ldfrag(smb, 0, 0);
#pragma unroll
        for (int kc = 0; kc < 2; kc++) {
            const int cur = kc & 1;
            if (kc < 1) ldfrag(smb, kc + 1, cur ^ 1);
#pragma unroll
            for (int tm = 0; tm < 2; tm++)
#pragma unroll
                for (int tn = 0; tn < 8; tn++)
                    mma_bf16(c[tm][tn], ah[cur][tm], bh[cur][tn]);
#pragma unroll
            for (int tm = 0; tm < 2; tm++)
#pragma unroll
                for (int tn = 0; tn < 8; tn++)
                    mma_bf16(c[tm][tn], ah[cur][tm], bl[cur][tn]);
#pragma unroll
            for (int tm = 0; tm < 2; tm++)
#pragma unroll
                for (int tn = 0; tn < 8; tn++)
                    mma_bf16(c[tm][tn], al[cur][tm], bh[cur][tn]);
        }
    }

    const int g = lane >> 2;
    const int t4 = lane & 3;
    const int bm = mb * 128;
    const int bn = nb * 128;
#pragma unroll
    for (int tm = 0; tm < 2; tm++) {
#pragma unroll
        for (int tn = 0; tn < 8; tn++) {
            int row0 = bm + warpM * 32 + tm * 16 + g;
            int col = bn + warpN * 64 + tn * 8 + t4 * 2;
#pragma unroll
            for (int hrow = 0; hrow < 2; hrow++) {
                int m = row0 + hrow * 8;
                float v0 = c[tm][tn][2 * hrow];
                float v1 = c[tm][tn][2 * hrow + 1];
                if (wmode == 1) {
                    wr_K_img(m, col, v0, v1);
                } else if (wmode == 2) {
                    wr_V_img(m, col, v0, v1);
                } else {
                    *reinterpret_cast<float2*>(Cout + (size_t)m * 1024 + col) =
                        make_float2(v0, v1);
                }
            }
        }
    }
}

__global__ __launch_bounds__(256, 1) void proj_img_kernel() {
    if (blockIdx.z == 0)
        gemm_img_body(g_xA, g_WkB, nullptr, 1);
    else
        gemm_img_body(g_xA, g_WvB, nullptr, 2);
}
__global__ __launch_bounds__(256, 1) void oproj_img_kernel(float* __restrict__ out) {
    gemm_img_body(g_OA, g_WoB, out, 0);
}

// ---------------------------------------------------------------------------
// Tensor-core attention, all-bf16 MMA:
//   S = K·V^T in 3x-bf16 (k16); softmax; O += P_bf16 · (V_hi + V_lo) (2-pass).
// l sums the SAME bf16-quantized p values the MMA consumes, so o is exactly
// softmax-with-quantized-weights (common-mode quantization absorbed).
// Per (b,h), q-block of 128 rows (CTA), key-tiles of 64. 256 thr = 8 warps;
// warp w owns rows w*16..w*16+15.
// SMEM: K bf16 images 32KB | P bf16 image 16KB | 2 stages x (VSB 16KB + VPB 16KB)
// ---------------------------------------------------------------------------
#define ATT_K 0
#define ATT_P 32768
#define ATT_STG 49152
#define ATT_STAGE_SZ 32768
#define ATT_SMEM_BYTES (49152 + 2 * ATT_STAGE_SZ)

__global__ __launch_bounds__(256, 1) void attn_mma_kernel() {
    extern __shared__ __align__(1024) char smc[];
    const uint32_t sbase = smem_u32(smc);
    const int tid = threadIdx.x;
    const int lane = tid & 31;
    const int w = tid >> 5;
    const int g = lane >> 2;
    const int t4 = lane & 3;
    const int hb = blockIdx.y;
    const int mb = blockIdx.x;
    const float SC = -32.0f * 1.4426950408889634f;

    const char* KAg = (const char*)g_KA + (size_t)(hb * 16 + mb) * 32768;
    const char* VSBg = (const char*)g_VSB + (size_t)hb * 32 * 16384;
    const char* VPBg = (const char*)g_VPB + (size_t)hb * 64 * 8192;

    auto issue_stage = [&](int i) {
        uint32_t stg = (uint32_t)(ATT_STG + (i & 1) * ATT_STAGE_SZ);
        if (tid < 128) {
            uint32_t d = sbase + stg + (uint32_t)tid * 128;
            const char* s = VSBg + (size_t)i * 16384 + tid * 128;
#pragma unroll
            for (int j = 0; j < 8; j++) CP16(d + j * 16, s + j * 16);
        } else {
            uint32_t d = sbase + stg + 16384 + (uint32_t)(tid - 128) * 128;
            const char* s = VPBg + (size_t)(2 * i) * 8192 + (tid - 128) * 128;
#pragma unroll
            for (int j = 0; j < 8; j++) CP16(d + j * 16, s + j * 16);
        }
        CP_COMMIT();
    };

    // Prologue: K (32KB, joins group 0) + stage0, then stage1
    {
        uint32_t d = sbase + (uint32_t)tid * 128;
        const char* s = KAg + tid * 128;
#pragma unroll
        for (int j = 0; j < 8; j++) CP16(d + j * 16, s + j * 16);
    }
    issue_stage(0);
    issue_stage(1);

    float o[8][4];
#pragma unroll
    for (int tn = 0; tn < 8; tn++)
#pragma unroll
        for (int q = 0; q < 4; q++) o[tn][q] = 0.0f;
    float m0 = -INFINITY, m1 = -INFINITY, l0 = 0.0f, l1 = 0.0f;

    for (int i = 0; i < 32; i++) {
        if (i < 31) CP_WAIT(1); else CP_WAIT(0);
        __syncthreads();
        const uint32_t stg = (uint32_t)(ATT_STG + (i & 1) * ATT_STAGE_SZ);

        // ---- S = K·V^T (128 x 64), 3x-bf16, frag double-buffer, pass-major ----
        float s[8][4];
#pragma unroll
        for (int tn = 0; tn < 8; tn++)
#pragma unroll
            for (int q = 0; q < 4; q++) s[tn][q] = 0.0f;

        uint32_t ah[2][4], al[2][4], bh[2][8][2], bl[2][8][2];
        auto ld_s_frag = [&](int kc, int buf) {
            int dc = kc >> 1;   // which 32-d chunk (16KB block)
            int kci = kc & 1;   // k16 chunk within block
            uint32_t aoff = (uint32_t)(ATT_K + dc * 16384) +
                            SW128((uint32_t)(kci * 8 + w) * 512 + lane * 16);
            uint4 h4 = *reinterpret_cast<const uint4*>(smc + aoff);
            uint4 l4 = *reinterpret_cast<const uint4*>(smc + aoff + 8192);
            ah[buf][0] = h4.x; ah[buf][1] = h4.y; ah[buf][2] = h4.z; ah[buf][3] = h4.w;
            al[buf][0] = l4.x; al[buf][1] = l4.y; al[buf][2] = l4.z; al[buf][3] = l4.w;
#pragma unroll
            for (int tn = 0; tn < 8; tn++) {
                uint32_t boff = stg + (uint32_t)(dc * 8192) +
                                SW128((uint32_t)(kci * 8 + tn) * 256 + lane * 8);
                uint2 bh2 = *reinterpret_cast<const uint2*>(smc + boff);
                uint2 bl2 = *reinterpret_cast<const uint2*>(smc + boff + 4096);
                bh[buf][tn][0] = bh2.x; bh[buf][tn][1] = bh2.y;
                bl[buf][tn][0] = bl2.x; bl[buf][tn][1] = bl2.y;
            }
        };

        ld_s_frag(0, 0);
#pragma unroll
        for (int kc = 0; kc < 4; kc++) {
            const int cur = kc & 1;
            if (kc < 3) ld_s_frag(kc + 1, cur ^ 1);
#pragma unroll
            for (int tn = 0; tn < 8; tn++) mma_bf16(s[tn], ah[cur], bh[cur][tn]);
#pragma unroll
            for (int tn = 0; tn < 8; tn++) mma_bf16(s[tn], ah[cur], bl[cur][tn]);
#pragma unroll
            for (int tn = 0; tn < 8; tn++) mma_bf16(s[tn], al[cur], bh[cur][tn]);
        }

        // ---- softmax over this 64-key tile (rows: w*16+g, w*16+g+8) ----
#pragma unroll
        for (int tn = 0; tn < 8; tn++)
#pragma unroll
            for (int q = 0; q < 4; q++) s[tn][q] *= SC;

        float mx0 = s[0][0], mx1 = s[0][2];
#pragma unroll
        for (int tn = 0; tn < 8; tn++) {
            mx0 = fmaxf(mx0, fmaxf(s[tn][0], s[tn][1]));
            mx1 = fmaxf(mx1, fmaxf(s[tn][2], s[tn][3]));
        }
        mx0 = fmaxf(mx0, __shfl_xor_sync(0xffffffffu, mx0, 1));
        mx0 = fmaxf(mx0, __shfl_xor_sync(0xffffffffu, mx0, 2));
        mx1 = fmaxf(mx1, __shfl_xor_sync(0xffffffffu, mx1, 1));
        mx1 = fmaxf(mx1, __shfl_xor_sync(0xffffffffu, mx1, 2));

        float mn0 = fmaxf(m0, mx0), mn1 = fmaxf(m1, mx1);
        float al0 = fast_exp2(m0 - mn0), al1 = fast_exp2(m1 - mn1);
        m0 = mn0; m1 = mn1;

        // Quantize p to bf16 (the exact values the PV MMA will consume), pack
        // the two adjacent keys per thread into one bf16x2 P-image word, and
        // sum the quantized values into l.
        float rs0 = 0.0f, rs1 = 0.0f;
        const int r0 = w * 16 + g;
#pragma unroll
        for (int tn = 0; tn < 8; tn++) {
            int pairIdx = tn * 4 + t4;  // 0..31 (keys 2*pairIdx, 2*pairIdx+1)
#pragma unroll
            for (int hrow = 0; hrow < 2; hrow++) {
                float mnv = hrow ? mn1 : mn0;
                float p0 = fast_exp2(s[tn][2 * hrow] - mnv);
                float p1 = fast_exp2(s[tn][2 * hrow + 1] - mnv);
                uint32_t pw = bf16x2_pack(p0, p1);
                float pq0 = __uint_as_float(pw << 16);
                float pq1 = __uint_as_float(pw & 0xFFFF0000u);
                if (hrow) rs1 += pq0 + pq1; else rs0 += pq0 + pq1;
                int row = r0 + hrow * 8;
                *reinterpret_cast<uint32_t*>(
                    smc + ATT_P + (pairIdx >> 4) * 8192 +
                    A16_off(row, pairIdx & 15)) = pw;
            }
        }
        rs0 += __shfl_xor_sync(0xffffffffu, rs0, 1);
        rs0 += __shfl_xor_sync(0xffffffffu, rs0, 2);
        rs1 += __shfl_xor_sync(0xffffffffu, rs1, 1);
        rs1 += __shfl_xor_sync(0xffffffffu, rs1, 2);
        l0 = l0 * al0 + rs0;
        l1 = l1 * al1 + rs1;
#pragma unroll
        for (int tn = 0; tn < 8; tn++) {
            o[tn][0] *= al0; o[tn][1] *= al0;
            o[tn][2] *= al1; o[tn][3] *= al1;
        }
        __syncwarp();

        // ---- O += P_bf16 · V (2-pass: V_hi, V_lo), frag double-buffer ----
        uint32_t pa[2][4], vh[2][8][2], vl[2][8][2];
        auto ld_pv_frag = [&](int kk, int buf) {   // kk = k16 step, 0..3
            int kc = kk >> 1;   // 32-key chunk
            int kci = kk & 1;   // k16 within chunk
            uint32_t poff = (uint32_t)(ATT_P + kc * 8192) +
                            SW128((uint32_t)(kci * 8 + w) * 512 + lane * 16);
            uint4 p4 = *reinterpret_cast<const uint4*>(smc + poff);
            pa[buf][0] = p4.x; pa[buf][1] = p4.y; pa[buf][2] = p4.z; pa[buf][3] = p4.w;
#pragma unroll
            for (int tn = 0; tn < 8; tn++) {
                uint32_t voff = stg + (uint32_t)(16384 + kc * 8192) +
                                SW128((uint32_t)(kci * 8 + tn) * 256 + lane * 8);
                uint2 vh2 = *reinterpret_cast<const uint2*>(smc + voff);
                uint2 vl2 = *reinterpret_cast<const uint2*>(smc + voff + 4096);
                vh[buf][tn][0] = vh2.x; vh[buf][tn][1] = vh2.y;
                vl[buf][tn][0] = vl2.x; vl[buf][tn][1] = vl2.y;
            }
        };

        ld_pv_frag(0, 0);
#pragma unroll
        for (int kk = 0; kk < 4; kk++) {
            const int cur = kk & 1;
            if (kk < 3) ld_pv_frag(kk + 1, cur ^ 1);
#pragma unroll
            for (int tn = 0; tn < 8; tn++) mma_bf16(o[tn], pa[cur], vh[cur][tn]);
#pragma unroll
            for (int tn = 0; tn < 8; tn++) mma_bf16(o[tn], pa[cur], vl[cur][tn]);
        }
        __syncthreads();
        if (i < 30) issue_stage(i + 2);
    }

    // ---- epilogue: normalize and write g_OA bf16 A-images ----
    const int b = hb >> 4;
    const int h = hb & 15;
    const float inv0 = 1.0f / l0, inv1 = 1.0f / l1;
    const int rbase = b * 2048 + mb * 128 + w * 16 + g;
#pragma unroll
    for (int tn = 0; tn < 8; tn++) {
        int d0 = h * 64 + tn * 8 + t4 * 2;
#pragma unroll
        for (int hrow = 0; hrow < 2; hrow++) {
            int row = rbase + hrow * 8;
            float inv = hrow ? inv1 : inv0;
            float v0 = o[tn][2 * hrow] * inv;
            float v1 = o[tn][2 * hrow + 1] * inv;
            char* blk = (char*)g_OA + (size_t)((row >> 7) * 32 + (d0 >> 5)) * 16384;
            uint32_t off = A16_off(row & 127, (d0 & 31) >> 1);
            uint32_t hw, lw;
            bf16_split(v0, v1, hw, lw);
            *reinterpret_cast<uint32_t*>(blk + off) = hw;
            *reinterpret_cast<uint32_t*>(blk + 8192 + off) = lw;
        }
    }
}

extern "C" void kernel_launch(void* const* d_in, const int* in_sizes, int n_in,
                              void* d_out, int out_size) {
    const float* x = (const float*)d_in[0];
    // d_in[1] = Wq (dead code in the reference dataflow)
    const float* Wk = (const float*)d_in[2];
    const float* Wv = (const float*)d_in[3];
    const float* Wo = (const float*)d_in[4];
    float* out = (float*)d_out;

    cudaFuncSetAttribute(proj_img_kernel, cudaFuncAttributeMaxDynamicSharedMemorySize,
                         GM_SMEM_BYTES);
    cudaFuncSetAttribute(oproj_img_kernel, cudaFuncAttributeMaxDynamicSharedMemorySize,
                         GM_SMEM_BYTES);
    cudaFuncSetAttribute(attn_mma_kernel, cudaFuncAttributeMaxDynamicSharedMemorySize,
                         ATT_SMEM_BYTES);

    // 1) Pre-split inputs into bf16 hi/lo fragment images
    split_kernel<<<dim3(32, 32, 4), 128>>>(x, Wk, Wv, Wo);

    // 2) K/V projections (3x-bf16); epilogues write K/V attention images
    proj_img_kernel<<<dim3(8, 32, 2), 256, GM_SMEM_BYTES>>>();

    // 3) Tensor-core attention (S: 3x-bf16, PV: 2x-bf16), writes g_OA images
    attn_mma_kernel<<<dim3(16, 32), 256, ATT_SMEM_BYTES>>>();

    // 4) Output projection (3x-bf16)
    oproj_img_kernel<<<dim3(8, 32), 256, GM_SMEM_BYTES>>>(out);
}

// round 12
// speedup vs baseline: 2.2002x; 1.1578x over previous
#include <cuda_runtime.h>
#include <cuda_fp16.h>
#include <math.h>
#include <stdint.h>

// Shapes (fixed): B=2, S=2048, E=1024, H=16, D=64
// Fragment-image planes (blocks = hi-plane | lo-plane):
//  g_xA : x as A op (bf16)   [mb(32)][kt(32)] blocks of 16KB (hi8K|lo8K)
//  g_OA : attn out as A op (fp16) same layout
//  g_WkB/g_WvB: weights as B op (bf16) [nb(8)][kt(32)] blocks of 16KB
//  g_WoB: Wo as B op (fp16; only hi used) same layout
//  g_KA : K as A op (bf16)   [hb(32)][mb(16)][dc(2)] blocks of 16KB
//  g_VSB: V as S-GEMM B op (bf16) [hb(32)][kb(32)][dc(2)] blocks of 8KB (hi4K|lo4K)
//  g_VPB: V as PV-GEMM B op (fp16 hi only) [hb(32)][kc(64)] blocks of 4KB
static __device__ float g_xA[8 * 1024 * 1024];
static __device__ float g_OA[8 * 1024 * 1024];
static __device__ float g_WkB[2 * 1024 * 1024];
static __device__ float g_WvB[2 * 1024 * 1024];
static __device__ float g_WoB[2 * 1024 * 1024];
static __device__ float g_KA[8 * 1024 * 1024];
static __device__ float g_VSB[8 * 1024 * 1024];
static __device__ float g_VPB[2 * 1024 * 1024];

__device__ __forceinline__ float fast_exp2(float x) {
    float y;
    asm("ex2.approx.ftz.f32 %0, %1;" : "=f"(y) : "f"(x));
    return y;
}
// bf16 helpers (v0 -> low half)
__device__ __forceinline__ uint32_t bf16x2_pack(float v0, float v1) {
    uint32_t r;
    asm("cvt.rn.bf16x2.f32 %0, %1, %2;" : "=r"(r) : "f"(v1), "f"(v0));
    return r;
}
__device__ __forceinline__ void bf16_split(float v0, float v1, uint32_t& hw,
                                           uint32_t& lw) {
    hw = bf16x2_pack(v0, v1);
    float h0 = __uint_as_float(hw << 16);
    float h1 = __uint_as_float(hw & 0xFFFF0000u);
    lw = bf16x2_pack(v0 - h0, v1 - h1);
}
// fp16 helpers (v0 -> low half)
__device__ __forceinline__ uint32_t f16x2_pack(float v0, float v1) {
    __half2 h = __floats2half2_rn(v0, v1);
    return *reinterpret_cast<uint32_t*>(&h);
}
__device__ __forceinline__ void f16_split(float v0, float v1, uint32_t& hw,
                                          uint32_t& lw) {
    __half2 h = __floats2half2_rn(v0, v1);
    hw = *reinterpret_cast<uint32_t*>(&h);
    float r0 = v0 - __low2float(h);
    float r1 = v1 - __high2float(h);
    __half2 l = __floats2half2_rn(r0, r1);
    lw = *reinterpret_cast<uint32_t*>(&l);
}

__device__ __forceinline__ void mma_bf16(float c[4], const uint32_t a[4],
                                         const uint32_t b[2]) {
    asm volatile(
        "mma.sync.aligned.m16n8k16.row.col.f32.bf16.bf16.f32 "
        "{%0,%1,%2,%3}, {%4,%5,%6,%7}, {%8,%9}, {%0,%1,%2,%3};"
        : "+f"(c[0]), "+f"(c[1]), "+f"(c[2]), "+f"(c[3])
        : "r"(a[0]), "r"(a[1]), "r"(a[2]), "r"(a[3]), "r"(b[0]), "r"(b[1]));
}
__device__ __forceinline__ void mma_f16(float c[4], const uint32_t a[4],
                                        const uint32_t b[2]) {
    asm volatile(
        "mma.sync.aligned.m16n8k16.row.col.f32.f16.f16.f32 "
        "{%0,%1,%2,%3}, {%4,%5,%6,%7}, {%8,%9}, {%0,%1,%2,%3};"
        : "+f"(c[0]), "+f"(c[1]), "+f"(c[2]), "+f"(c[3])
        : "r"(a[0]), "r"(a[1]), "r"(a[2]), "r"(a[3]), "r"(b[0]), "r"(b[1]));
}
__device__ __forceinline__ uint32_t smem_u32(const void* p) {
    uint32_t a;
    asm("{ .reg .u64 t; cvta.to.shared.u64 t, %1; cvt.u32.u64 %0, t; }"
        : "=r"(a) : "l"(p));
    return a;
}

#define SW128(o) ((o) ^ (((o) >> 3) & 0x70))
#define CP16(d, s) \
    asm volatile("cp.async.cg.shared.global [%0], [%1], 16;" ::"r"(d), "l"(s) : "memory")
#define CP_COMMIT() asm volatile("cp.async.commit_group;" ::: "memory")
#define CP_WAIT(n) asm volatile("cp.async.wait_group %0;" ::"n"(n) : "memory")

// ---- 16-bit image word offsets (p = k>>1, pair index within 32-k tile) ----
// A-plane 8KB: 128 rows x 32 k
__device__ __forceinline__ uint32_t A16_off(int row, int p) {
    int kc = p >> 3, pi = p & 7;
    uint32_t base = (uint32_t)(kc * 8 + (row >> 4)) << 9;
    uint32_t lane = (uint32_t)(((row & 7) << 2) | (pi & 3));
    uint32_t w = (uint32_t)(((pi >> 2) << 1) | ((row >> 3) & 1));
    return SW128(base + (lane << 4) + (w << 2));
}
// B-plane 8KB: 128 n x 32 k
__device__ __forceinline__ uint32_t B16_off(int n, int p) {
    int kc = p >> 3, pi = p & 7;
    uint32_t base = (uint32_t)(kc * 16 + (n >> 3)) << 8;
    uint32_t lane = (uint32_t)(((n & 7) << 2) | (pi & 3));
    uint32_t w = (uint32_t)(pi >> 2);
    return SW128(base + (lane << 3) + (w << 2));
}
// B-plane 4KB: 64 n x 32 k
__device__ __forceinline__ uint32_t B16_off64(int n, int p) {
    int kc = p >> 3, pi = p & 7;
    uint32_t base = (uint32_t)(kc * 8 + (n >> 3)) << 8;
    uint32_t lane = (uint32_t)(((n & 7) << 2) | (pi & 3));
    uint32_t w = (uint32_t)(pi >> 2);
    return SW128(base + (lane << 3) + (w << 2));
}

// ---------------------------------------------------------------------------
// Split kernel: fp32 -> hi/lo fragment images.
// z=0: x -> bf16 A-images; z=1,2: Wk/Wv -> bf16 B-images; z=3: Wo -> fp16.
// ---------------------------------------------------------------------------
__global__ __launch_bounds__(128) void split_kernel(const float* __restrict__ x,
                                                    const float* __restrict__ Wk,
                                                    const float* __restrict__ Wv,
                                                    const float* __restrict__ Wo) {
    const int z = blockIdx.z;
    const int mb = blockIdx.y;
    const int kt = blockIdx.x;
    const float* src;
    float* dst;
    int isA;
    if (z == 0) {
        src = x; dst = g_xA; isA = 1;
    } else {
        if (mb >= 8) return;
        src = (z == 1) ? Wk : (z == 2) ? Wv : Wo;
        dst = (z == 1) ? g_WkB : (z == 2) ? g_WvB : g_WoB;
        isA = 0;
    }
    char* blk = (char*)dst + (size_t)(mb * 32 + kt) * 16384;
    const int tid = threadIdx.x;
#pragma unroll
    for (int e = 0; e < 16; e++) {
        int idx = e * 128 + tid;
        int row = idx >> 4;
        int p = idx & 15;
        const float* r = src + (size_t)(mb * 128 + row) * 1024 + kt * 32 + p * 2;
        uint32_t hw, lw;
        if (z == 3) f16_split(r[0], r[1], hw, lw);
        else bf16_split(r[0], r[1], hw, lw);
        uint32_t off = isA ? A16_off(row, p) : B16_off(row, p);
        *reinterpret_cast<uint32_t*>(blk + off) = hw;
        *reinterpret_cast<uint32_t*>(blk + 8192 + off) = lw;
    }
}

// ---------------------------------------------------------------------------
// Image GEMM: CTA 128x128, K=1024. 256 threads = 8 warps = 4(M) x 2(N),
// warp tile 32x64. 3-stage cp.async (32KB/stage), one barrier per K-tile,
// fragment double-buffering, pass-major issue.
// WMODE 1/2 (proj K/V): bf16 3-pass (hh + hl + lh).
// WMODE 0  (oproj):     fp16 2-pass (Ah·Bh + Al·Bh); B-lo unused/unloaded.
// ---------------------------------------------------------------------------
#define GM_SMEM_BYTES (3 * 32768)

__device__ __forceinline__ void wr_K_img(int m, int col, float v0, float v1) {
    int s = m & 2047;
    int hb = ((m >> 11) << 4) + (col >> 6);
    int d = col & 63;
    char* blk = (char*)g_KA +
                (size_t)((hb * 16 + (s >> 7)) * 2 + (d >> 5)) * 16384;
    uint32_t off = A16_off(s & 127, (d & 31) >> 1);
    uint32_t hw, lw;
    bf16_split(v0, v1, hw, lw);
    *reinterpret_cast<uint32_t*>(blk + off) = hw;
    *reinterpret_cast<uint32_t*>(blk + 8192 + off) = lw;
}
__device__ __forceinline__ void wr_V_img(int m, int col, float v0, float v1) {
    int s = m & 2047;
    int hb = ((m >> 11) << 4) + (col >> 6);
    int d = col & 63;
    {   // VSB: bf16, n = key (64), k = d (32)
        char* blk = (char*)g_VSB +
                    (size_t)((hb * 32 + (s >> 6)) * 2 + (d >> 5)) * 8192;
        uint32_t off = B16_off64(s & 63, (d & 31) >> 1);
        uint32_t hw, lw;
        bf16_split(v0, v1, hw, lw);
        *reinterpret_cast<uint32_t*>(blk + off) = hw;
        *reinterpret_cast<uint32_t*>(blk + 4096 + off) = lw;
    }
    {   // VPB: fp16 HI ONLY, n = d (64), k = key (32). Adjacent keys live in
        // adjacent g-lanes (lane ^ 4); even-g lanes pack (key s, key s+1).
        float u0 = __shfl_xor_sync(0xffffffffu, v0, 4);
        float u1 = __shfl_xor_sync(0xffffffffu, v1, 4);
        int lane = (int)(threadIdx.x & 31);
        if (!(lane & 4)) {
            char* blk = (char*)g_VPB + (size_t)(hb * 64 + (s >> 5)) * 4096;
            uint32_t p = (uint32_t)((s & 31) >> 1);
            *reinterpret_cast<uint32_t*>(blk + B16_off64(d, p)) =
                f16x2_pack(v0, u0);
            *reinterpret_cast<uint32_t*>(blk + B16_off64(d + 1, p)) =
                f16x2_pack(v1, u1);
        }
    }
}

template <int WMODE>
__device__ void gemm_img_body(const float* __restrict__ Aimg,
                              const float* __restrict__ Bimg,
                              float* __restrict__ Cout) {
    extern __shared__ __align__(1024) char smc[];
    const uint32_t sbase = smem_u32(smc);
    const int tid = threadIdx.x;
    const int lane = tid & 31;
    const int wid = tid >> 5;
    const int warpM = wid & 3;
    const int warpN = wid >> 2;
    const int mb = blockIdx.y;
    const int nb = blockIdx.x;

    float c[2][8][4];
#pragma unroll
    for (int i = 0; i < 2; i++)
#pragma unroll
        for (int j = 0; j < 8; j++)
#pragma unroll
            for (int q = 0; q < 4; q++) c[i][j][q] = 0.0f;

    uint32_t ah[2][2][4], al[2][2][4], bh[2][8][2], bl[2][8][2];

    const char* Abase = (const char*)(Aimg) + (size_t)mb * 32 * 16384;
    const char* Bbase = (const char*)(Bimg) + (size_t)nb * 32 * 16384;

    auto issue = [&](int kt) {
        int st = kt % 3;
        if (tid < 128) {
            uint32_t d = sbase + (uint32_t)(st * 32768) + (uint32_t)tid * 128;
            const char* s = Abase + (size_t)kt * 16384 + tid * 128;
#pragma unroll
            for (int j = 0; j < 8; j++) CP16(d + j * 16, s + j * 16);
        } else {
            uint32_t d = sbase + (uint32_t)(st * 32768 + 16384) +
                         (uint32_t)(tid - 128) * 128;
            const char* s = Bbase + (size_t)kt * 16384 + (tid - 128) * 128;
#pragma unroll
            for (int j = 0; j < 8; j++) CP16(d + j * 16, s + j * 16);
        }
        CP_COMMIT();
    };

    auto ldfrag = [&](const char* smb, int kc, int buf) {
#pragma unroll
        for (int tm = 0; tm < 2; tm++) {
            uint32_t off = SW128((uint32_t)(kc * 8 + warpM * 2 + tm) * 512 + lane * 16);
            uint4 h = *reinterpret_cast<const uint4*>(smb + off);
            ah[buf][tm][0] = h.x; ah[buf][tm][1] = h.y;
            ah[buf][tm][2] = h.z; ah[buf][tm][3] = h.w;
            uint4 l = *reinterpret_cast<const uint4*>(smb + 8192 + off);
            al[buf][tm][0] = l.x; al[buf][tm][1] = l.y;
            al[buf][tm][2] = l.z; al[buf][tm][3] = l.w;
        }
#pragma unroll
        for (int tn = 0; tn < 8; tn++) {
            uint32_t off = SW128((uint32_t)(kc * 16 + warpN * 8 + tn) * 256 + lane * 8);
            uint2 h = *reinterpret_cast<const uint2*>(smb + 16384 + off);
            bh[buf][tn][0] = h.x; bh[buf][tn][1] = h.y;
            if (WMODE != 0) {
                uint2 l = *reinterpret_cast<const uint2*>(smb + 24576 + off);
                bl[buf][tn][0] = l.x; bl[buf][tn][1] = l.y;
            }
        }
    };

    issue(0);
    issue(1);
    for (int kt = 0; kt < 32; kt++) {
        if (kt < 31) CP_WAIT(1); else CP_WAIT(0);
        __syncthreads();
        if (kt + 2 < 32) issue(kt + 2);
        const char* smb = smc + (kt % 3) * 32768;

        ldfrag(smb, 0, 0);
#pragma unroll
        for (int kc = 0; kc < 2; kc++) {
            const int cur = kc & 1;
            if (kc < 1) ldfrag(smb, kc + 1, cur ^ 1);
            if (WMODE == 0) {
                // fp16 2-pass: Ah·Bh + Al·Bh
#pragma unroll
                for (int tm = 0; tm < 2; tm++)
#pragma unroll
                    for (int tn = 0; tn < 8; tn++)
                        mma_f16(c[tm][tn], ah[cur][tm], bh[cur][tn]);
#pragma unroll
                for (int tm = 0; tm < 2; tm++)
#pragma unroll
                    for (int tn = 0; tn < 8; tn++)
                        mma_f16(c[tm][tn], al[cur][tm], bh[cur][tn]);
            } else {
                // bf16 3-pass: Ah·Bh + Ah·Bl + Al·Bh
#pragma unroll
                for (int tm = 0; tm < 2; tm++)
#pragma unroll
                    for (int tn = 0; tn < 8; tn++)
                        mma_bf16(c[tm][tn], ah[cur][tm], bh[cur][tn]);
#pragma unroll
                for (int tm = 0; tm < 2; tm++)
#pragma unroll
                    for (int tn = 0; tn < 8; tn++)
                        mma_bf16(c[tm][tn], ah[cur][tm], bl[cur][tn]);
#pragma unroll
                for (int tm = 0; tm < 2; tm++)
#pragma unroll
                    for (int tn = 0; tn < 8; tn++)
                        mma_bf16(c[tm][tn], al[cur][tm], bh[cur][tn]);
            }
        }
    }

    const int g = lane >> 2;
    const int t4 = lane & 3;
    const int bm = mb * 128;
    const int bn = nb * 128;
#pragma unroll
    for (int tm = 0; tm < 2; tm++) {
#pragma unroll
        for (int tn = 0; tn < 8; tn++) {
            int row0 = bm + warpM * 32 + tm * 16 + g;
            int col = bn + warpN * 64 + tn * 8 + t4 * 2;
#pragma unroll
            for (int hrow = 0; hrow < 2; hrow++) {
                int m = row0 + hrow * 8;
                float v0 = c[tm][tn][2 * hrow];
                float v1 = c[tm][tn][2 * hrow + 1];
                if (WMODE == 1) {
                    wr_K_img(m, col, v0, v1);
                } else if (WMODE == 2) {
                    wr_V_img(m, col, v0, v1);
                } else {
                    *reinterpret_cast<float2*>(Cout + (size_t)m * 1024 + col) =
                        make_float2(v0, v1);
                }
            }
        }
    }
}

__global__ __launch_bounds__(256, 1) void proj_img_kernel() {
    if (blockIdx.z == 0)
        gemm_img_body<1>(g_xA, g_WkB, nullptr);
    else
        gemm_img_body<2>(g_xA, g_WvB, nullptr);
}
__global__ __launch_bounds__(256, 1) void oproj_img_kernel(float* __restrict__ out) {
    gemm_img_body<0>(g_OA, g_WoB, out);
}

// ---------------------------------------------------------------------------
// Tensor-core attention:
//   S = K·V^T in 3x-bf16 (k16); softmax; O += P_fp16 · V_fp16hi (1 pass).
// l sums the SAME fp16-quantized p values the MMA consumes (common-mode
// quantization absorbed); V_lo drop costs ~2^-11 relative on O.
// Per (b,h), q-block of 128 rows (CTA), key-tiles of 64. 256 thr = 8 warps;
// warp w owns rows w*16..w*16+15.
// SMEM: K bf16 images 32KB | P fp16 image 16KB | 2 stages x (VSB 16KB + VPB 8KB)
// ---------------------------------------------------------------------------
#define ATT_K 0
#define ATT_P 32768
#define ATT_STG 49152
#define ATT_STAGE_SZ 24576
#define ATT_SMEM_BYTES (49152 + 2 * ATT_STAGE_SZ)

__global__ __launch_bounds__(256, 1) void attn_mma_kernel() {
    extern __shared__ __align__(1024) char smc[];
    const uint32_t sbase = smem_u32(smc);
    const int tid = threadIdx.x;
    const int lane = tid & 31;
    const int w = tid >> 5;
    const int g = lane >> 2;
    const int t4 = lane & 3;
    const int hb = blockIdx.y;
    const int mb = blockIdx.x;
    const float SC = -32.0f * 1.4426950408889634f;

    const char* KAg = (const char*)g_KA + (size_t)(hb * 16 + mb) * 32768;
    const char* VSBg = (const char*)g_VSB + (size_t)hb * 32 * 16384;
    const char* VPBg = (const char*)g_VPB + (size_t)hb * 64 * 4096;

    auto issue_stage = [&](int i) {
        uint32_t stg = (uint32_t)(ATT_STG + (i & 1) * ATT_STAGE_SZ);
        if (tid < 128) {
            uint32_t d = sbase + stg + (uint32_t)tid * 128;
            const char* s = VSBg + (size_t)i * 16384 + tid * 128;
#pragma unroll
            for (int j = 0; j < 8; j++) CP16(d + j * 16, s + j * 16);
        } else {
            uint32_t d = sbase + stg + 16384 + (uint32_t)(tid - 128) * 64;
            const char* s = VPBg + (size_t)(2 * i) * 4096 + (tid - 128) * 64;
#pragma unroll
            for (int j = 0; j < 4; j++) CP16(d + j * 16, s + j * 16);
        }
        CP_COMMIT();
    };

    // Prologue: K (32KB, joins group 0) + stage0, then stage1
    {
        uint32_t d = sbase + (uint32_t)tid * 128;
        const char* s = KAg + tid * 128;
#pragma unroll
        for (int j = 0; j < 8; j++) CP16(d + j * 16, s + j * 16);
    }
    issue_stage(0);
    issue_stage(1);

    float o[8][4];
#pragma unroll
    for (int tn = 0; tn < 8; tn++)
#pragma unroll
        for (int q = 0; q < 4; q++) o[tn][q] = 0.0f;
    float m0 = -INFINITY, m1 = -INFINITY, l0 = 0.0f, l1 = 0.0f;

    for (int i = 0; i < 32; i++) {
        if (i < 31) CP_WAIT(1); else CP_WAIT(0);
        __syncthreads();
        const uint32_t stg = (uint32_t)(ATT_STG + (i & 1) * ATT_STAGE_SZ);

        // ---- S = K·V^T (128 x 64), 3x-bf16, frag double-buffer, pass-major ----
        float s[8][4];
#pragma unroll
        for (int tn = 0; tn < 8; tn++)
#pragma unroll
            for (int q = 0; q < 4; q++) s[tn][q] = 0.0f;

        uint32_t ah[2][4], al[2][4], bh[2][8][2], bl[2][8][2];
        auto ld_s_frag = [&](int kc, int buf) {
            int dc = kc >> 1;   // which 32-d chunk (16KB block)
            int kci = kc & 1;   // k16 chunk within block
            uint32_t aoff = (uint32_t)(ATT_K + dc * 16384) +
                            SW128((uint32_t)(kci * 8 + w) * 512 + lane * 16);
            uint4 h4 = *reinterpret_cast<const uint4*>(smc + aoff);
            uint4 l4 = *reinterpret_cast<const uint4*>(smc + aoff + 8192);
            ah[buf][0] = h4.x; ah[buf][1] = h4.y; ah[buf][2] = h4.z; ah[buf][3] = h4.w;
            al[buf][0] = l4.x; al[buf][1] = l4.y; al[buf][2] = l4.z; al[buf][3] = l4.w;
#pragma unroll
            for (int tn = 0; tn < 8; tn++) {
                uint32_t boff = stg + (uint32_t)(dc * 8192) +
                                SW128((uint32_t)(kci * 8 + tn) * 256 + lane * 8);
                uint2 bh2 = *reinterpret_cast<const uint2*>(smc + boff);
                uint2 bl2 = *reinterpret_cast<const uint2*>(smc + boff + 4096);
                bh[buf][tn][0] = bh2.x; bh[buf][tn][1] = bh2.y;
                bl[buf][tn][0] = bl2.x; bl[buf][tn][1] = bl2.y;
            }
        };

        ld_s_frag(0, 0);
#pragma unroll
        for (int kc = 0; kc < 4; kc++) {
            const int cur = kc & 1;
            if (kc < 3) ld_s_frag(kc + 1, cur ^ 1);
#pragma unroll
            for (int tn = 0; tn < 8; tn++) mma_bf16(s[tn], ah[cur], bh[cur][tn]);
#pragma unroll
            for (int tn = 0; tn < 8; tn++) mma_bf16(s[tn], ah[cur], bl[cur][tn]);
#pragma unroll
            for (int tn = 0; tn < 8; tn++) mma_bf16(s[tn], al[cur], bh[cur][tn]);
        }

        // ---- softmax over this 64-key tile (rows: w*16+g, w*16+g+8) ----
#pragma unroll
        for (int tn = 0; tn < 8; tn++)
#pragma unroll
            for (int q = 0; q < 4; q++) s[tn][q] *= SC;

        float mx0 = s[0][0], mx1 = s[0][2];
#pragma unroll
        for (int tn = 0; tn < 8; tn++) {
            mx0 = fmaxf(mx0, fmaxf(s[tn][0], s[tn][1]));
            mx1 = fmaxf(mx1, fmaxf(s[tn][2], s[tn][3]));
        }
        mx0 = fmaxf(mx0, __shfl_xor_sync(0xffffffffu, mx0, 1));
        mx0 = fmaxf(mx0, __shfl_xor_sync(0xffffffffu, mx0, 2));
        mx1 = fmaxf(mx1, __shfl_xor_sync(0xffffffffu, mx1, 1));
        mx1 = fmaxf(mx1, __shfl_xor_sync(0xffffffffu, mx1, 2));

        float mn0 = fmaxf(m0, mx0), mn1 = fmaxf(m1, mx1);
        float al0 = fast_exp2(m0 - mn0), al1 = fast_exp2(m1 - mn1);
        m0 = mn0; m1 = mn1;

        // Quantize p to fp16 (the exact values the PV MMA consumes), pack two
        // adjacent keys per thread into one fp16x2 P-image word, sum quantized
        // values into l.
        float rs0 = 0.0f, rs1 = 0.0f;
        const int r0 = w * 16 + g;
#pragma unroll
        for (int tn = 0; tn < 8; tn++) {
            int pairIdx = tn * 4 + t4;  // 0..31 (keys 2*pairIdx, 2*pairIdx+1)
#pragma unroll
            for (int hrow = 0; hrow < 2; hrow++) {
                float mnv = hrow ? mn1 : mn0;
                float p0 = fast_exp2(s[tn][2 * hrow] - mnv);
                float p1 = fast_exp2(s[tn][2 * hrow + 1] - mnv);
                __half2 ph = __floats2half2_rn(p0, p1);
                uint32_t pw = *reinterpret_cast<uint32_t*>(&ph);
                float pq0 = __low2float(ph);
                float pq1 = __high2float(ph);
                if (hrow) rs1 += pq0 + pq1; else rs0 += pq0 + pq1;
                int row = r0 + hrow * 8;
                *reinterpret_cast<uint32_t*>(
                    smc + ATT_P + (pairIdx >> 4) * 8192 +
                    A16_off(row, pairIdx & 15)) = pw;
            }
        }
        rs0 += __shfl_xor_sync(0xffffffffu, rs0, 1);
        rs0 += __shfl_xor_sync(0xffffffffu, rs0, 2);
        rs1 += __shfl_xor_sync(0xffffffffu, rs1, 1);
        rs1 += __shfl_xor_sync(0xffffffffu, rs1, 2);
        l0 = l0 * al0 + rs0;
        l1 = l1 * al1 + rs1;
#pragma unroll
        for (int tn = 0; tn < 8; tn++) {
            o[tn][0] *= al0; o[tn][1] *= al0;
            o[tn][2] *= al1; o[tn][3] *= al1;
        }
        __syncwarp();

        // ---- O += P_fp16 · V_fp16hi (single pass), frag double-buffer ----
        uint32_t pa[2][4], vh[2][8][2];
        auto ld_pv_frag = [&](int kk, int buf) {   // kk = k16 step, 0..3
            int kc = kk >> 1;   // 32-key chunk
            int kci = kk & 1;   // k16 within chunk
            uint32_t poff = (uint32_t)(ATT_P + kc * 8192) +
                            SW128((uint32_t)(kci * 8 + w) * 512 + lane * 16);
            uint4 p4 = *reinterpret_cast<const uint4*>(smc + poff);
            pa[buf][0] = p4.x; pa[buf][1] = p4.y; pa[buf][2] = p4.z; pa[buf][3] = p4.w;
#pragma unroll
            for (int tn = 0; tn < 8; tn++) {
                uint32_t voff = stg + (uint32_t)(16384 + kc * 4096) +
                                SW128((uint32_t)(kci * 8 + tn) * 256 + lane * 8);
                uint2 vh2 = *reinterpret_cast<const uint2*>(smc + voff);
                vh[buf][tn][0] = vh2.x; vh[buf][tn][1] = vh2.y;
            }
        };

        ld_pv_frag(0, 0);
#pragma unroll
        for (int kk = 0; kk < 4; kk++) {
            const int cur = kk & 1;
            if (kk < 3) ld_pv_frag(kk + 1, cur ^ 1);
#pragma unroll
            for (int tn = 0; tn < 8; tn++) mma_f16(o[tn], pa[cur], vh[cur][tn]);
        }
        __syncthreads();
        if (i < 30) issue_stage(i + 2);
    }

    // ---- epilogue: normalize and write g_OA fp16 A-images (hi+lo) ----
    const int b = hb >> 4;
    const int h = hb & 15;
    const float inv0 = 1.0f / l0, inv1 = 1.0f / l1;
    const int rbase = b * 2048 + mb * 128 + w * 16 + g;
#pragma unroll
    for (int tn = 0; tn < 8; tn++) {
        int d0 = h * 64 + tn * 8 + t4 * 2;
#pragma unroll
        for (int hrow = 0; hrow < 2; hrow++) {
            int row = rbase + hrow * 8;
            float inv = hrow ? inv1 : inv0;
            float v0 = o[tn][2 * hrow] * inv;
            float v1 = o[tn][2 * hrow + 1] * inv;
            char* blk = (char*)g_OA + (size_t)((row >> 7) * 32 + (d0 >> 5)) * 16384;
            uint32_t off = A16_off(row & 127, (d0 & 31) >> 1);
            uint32_t hw, lw;
            f16_split(v0, v1, hw, lw);
            *reinterpret_cast<uint32_t*>(blk + off) = hw;
            *reinterpret_cast<uint32_t*>(blk + 8192 + off) = lw;
        }
    }
}

extern "C" void kernel_launch(void* const* d_in, const int* in_sizes, int n_in,
                              void* d_out, int out_size) {
    const float* x = (const float*)d_in[0];
    // d_in[1] = Wq (dead code in the reference dataflow)
    const float* Wk = (const float*)d_in[2];
    const float* Wv = (const float*)d_in[3];
    const float* Wo = (const float*)d_in[4];
    float* out = (float*)d_out;

    cudaFuncSetAttribute(proj_img_kernel, cudaFuncAttributeMaxDynamicSharedMemorySize,
                         GM_SMEM_BYTES);
    cudaFuncSetAttribute(oproj_img_kernel, cudaFuncAttributeMaxDynamicSharedMemorySize,
                         GM_SMEM_BYTES);
    cudaFuncSetAttribute(attn_mma_kernel, cudaFuncAttributeMaxDynamicSharedMemorySize,
                         ATT_SMEM_BYTES);

    // 1) Pre-split inputs into fragment images (x/Wk/Wv bf16, Wo fp16)
    split_kernel<<<dim3(32, 32, 4), 128>>>(x, Wk, Wv, Wo);

    // 2) K/V projections (3x-bf16); epilogues write K/V attention images
    proj_img_kernel<<<dim3(8, 32, 2), 256, GM_SMEM_BYTES>>>();

    // 3) Tensor-core attention (S: 3x-bf16, PV: 1x-fp16), writes g_OA fp16 images
    attn_mma_kernel<<<dim3(16, 32), 256, ATT_SMEM_BYTES>>>();

    // 4) Output projection (2x-fp16)
    oproj_img_kernel<<<dim3(8, 32), 256, GM_SMEM_BYTES>>>(out);
}

// round 13
// speedup vs baseline: 2.4444x; 1.1110x over previous
#include <cuda_runtime.h>
#include <cuda_fp16.h>
#include <math.h>
#include <stdint.h>

// Shapes (fixed): B=2, S=2048, E=1024, H=16, D=64
// Fragment-image planes (blocks = hi-plane | lo-plane):
//  g_xA : x as A op (bf16)   [mb(32)][kt(32)] blocks of 16KB (hi8K|lo8K)
//  g_OA : attn out as A op (fp16; only hi used) same layout
//  g_WkB/g_WvB: weights as B op (bf16) [nb(8)][kt(32)] blocks of 16KB
//  g_WoB: Wo as B op (fp16; only hi used) same layout
//  g_KA : K as A op (bf16)   [hb(32)][mb(16)][dc(2)] blocks of 16KB
//  g_VSB: V as S-GEMM B op (bf16) [hb(32)][kb(32)][dc(2)] blocks of 8KB (hi4K|lo4K)
//  g_VPB: V as PV-GEMM B op (fp16 hi only) [hb(32)][kc(64)] blocks of 4KB
static __device__ float g_xA[8 * 1024 * 1024];
static __device__ float g_OA[8 * 1024 * 1024];
static __device__ float g_WkB[2 * 1024 * 1024];
static __device__ float g_WvB[2 * 1024 * 1024];
static __device__ float g_WoB[2 * 1024 * 1024];
static __device__ float g_KA[8 * 1024 * 1024];
static __device__ float g_VSB[8 * 1024 * 1024];
static __device__ float g_VPB[2 * 1024 * 1024];

__device__ __forceinline__ float fast_exp2(float x) {
    float y;
    asm("ex2.approx.ftz.f32 %0, %1;" : "=f"(y) : "f"(x));
    return y;
}
// bf16 helpers (v0 -> low half)
__device__ __forceinline__ uint32_t bf16x2_pack(float v0, float v1) {
    uint32_t r;
    asm("cvt.rn.bf16x2.f32 %0, %1, %2;" : "=r"(r) : "f"(v1), "f"(v0));
    return r;
}
__device__ __forceinline__ void bf16_split(float v0, float v1, uint32_t& hw,
                                           uint32_t& lw) {
    hw = bf16x2_pack(v0, v1);
    float h0 = __uint_as_float(hw << 16);
    float h1 = __uint_as_float(hw & 0xFFFF0000u);
    lw = bf16x2_pack(v0 - h0, v1 - h1);
}
// fp16 helpers (v0 -> low half)
__device__ __forceinline__ uint32_t f16x2_pack(float v0, float v1) {
    __half2 h = __floats2half2_rn(v0, v1);
    return *reinterpret_cast<uint32_t*>(&h);
}
__device__ __forceinline__ void f16_split(float v0, float v1, uint32_t& hw,
                                          uint32_t& lw) {
    __half2 h = __floats2half2_rn(v0, v1);
    hw = *reinterpret_cast<uint32_t*>(&h);
    float r0 = v0 - __low2float(h);
    float r1 = v1 - __high2float(h);
    __half2 l = __floats2half2_rn(r0, r1);
    lw = *reinterpret_cast<uint32_t*>(&l);
}

__device__ __forceinline__ void mma_bf16(float c[4], const uint32_t a[4],
                                         const uint32_t b[2]) {
    asm volatile(
        "mma.sync.aligned.m16n8k16.row.col.f32.bf16.bf16.f32 "
        "{%0,%1,%2,%3}, {%4,%5,%6,%7}, {%8,%9}, {%0,%1,%2,%3};"
        : "+f"(c[0]), "+f"(c[1]), "+f"(c[2]), "+f"(c[3])
        : "r"(a[0]), "r"(a[1]), "r"(a[2]), "r"(a[3]), "r"(b[0]), "r"(b[1]));
}
__device__ __forceinline__ void mma_f16(float c[4], const uint32_t a[4],
                                        const uint32_t b[2]) {
    asm volatile(
        "mma.sync.aligned.m16n8k16.row.col.f32.f16.f16.f32 "
        "{%0,%1,%2,%3}, {%4,%5,%6,%7}, {%8,%9}, {%0,%1,%2,%3};"
        : "+f"(c[0]), "+f"(c[1]), "+f"(c[2]), "+f"(c[3])
        : "r"(a[0]), "r"(a[1]), "r"(a[2]), "r"(a[3]), "r"(b[0]), "r"(b[1]));
}
__device__ __forceinline__ uint32_t smem_u32(const void* p) {
    uint32_t a;
    asm("{ .reg .u64 t; cvta.to.shared.u64 t, %1; cvt.u32.u64 %0, t; }"
        : "=r"(a) : "l"(p));
    return a;
}

#define SW128(o) ((o) ^ (((o) >> 3) & 0x70))
#define CP16(d, s) \
    asm volatile("cp.async.cg.shared.global [%0], [%1], 16;" ::"r"(d), "l"(s) : "memory")
#define CP_COMMIT() asm volatile("cp.async.commit_group;" ::: "memory")
#define CP_WAIT(n) asm volatile("cp.async.wait_group %0;" ::"n"(n) : "memory")

// ---- 16-bit image word offsets (p = k>>1, pair index within 32-k tile) ----
// A-plane 8KB: 128 rows x 32 k
__device__ __forceinline__ uint32_t A16_off(int row, int p) {
    int kc = p >> 3, pi = p & 7;
    uint32_t base = (uint32_t)(kc * 8 + (row >> 4)) << 9;
    uint32_t lane = (uint32_t)(((row & 7) << 2) | (pi & 3));
    uint32_t w = (uint32_t)(((pi >> 2) << 1) | ((row >> 3) & 1));
    return SW128(base + (lane << 4) + (w << 2));
}
// B-plane 8KB: 128 n x 32 k
__device__ __forceinline__ uint32_t B16_off(int n, int p) {
    int kc = p >> 3, pi = p & 7;
    uint32_t base = (uint32_t)(kc * 16 + (n >> 3)) << 8;
    uint32_t lane = (uint32_t)(((n & 7) << 2) | (pi & 3));
    uint32_t w = (uint32_t)(pi >> 2);
    return SW128(base + (lane << 3) + (w << 2));
}
// B-plane 4KB: 64 n x 32 k
__device__ __forceinline__ uint32_t B16_off64(int n, int p) {
    int kc = p >> 3, pi = p & 7;
    uint32_t base = (uint32_t)(kc * 8 + (n >> 3)) << 8;
    uint32_t lane = (uint32_t)(((n & 7) << 2) | (pi & 3));
    uint32_t w = (uint32_t)(pi >> 2);
    return SW128(base + (lane << 3) + (w << 2));
}

// ---------------------------------------------------------------------------
// Split kernel: fp32 -> hi/lo fragment images.
// z=0: x -> bf16 A-images; z=1,2: Wk/Wv -> bf16 B-images; z=3: Wo -> fp16.
// ---------------------------------------------------------------------------
__global__ __launch_bounds__(128) void split_kernel(const float* __restrict__ x,
                                                    const float* __restrict__ Wk,
                                                    const float* __restrict__ Wv,
                                                    const float* __restrict__ Wo) {
    const int z = blockIdx.z;
    const int mb = blockIdx.y;
    const int kt = blockIdx.x;
    const float* src;
    float* dst;
    int isA;
    if (z == 0) {
        src = x; dst = g_xA; isA = 1;
    } else {
        if (mb >= 8) return;
        src = (z == 1) ? Wk : (z == 2) ? Wv : Wo;
        dst = (z == 1) ? g_WkB : (z == 2) ? g_WvB : g_WoB;
        isA = 0;
    }
    char* blk = (char*)dst + (size_t)(mb * 32 + kt) * 16384;
    const int tid = threadIdx.x;
#pragma unroll
    for (int e = 0; e < 16; e++) {
        int idx = e * 128 + tid;
        int row = idx >> 4;
        int p = idx & 15;
        const float* r = src + (size_t)(mb * 128 + row) * 1024 + kt * 32 + p * 2;
        uint32_t hw, lw;
        if (z == 3) f16_split(r[0], r[1], hw, lw);
        else bf16_split(r[0], r[1], hw, lw);
        uint32_t off = isA ? A16_off(row, p) : B16_off(row, p);
        *reinterpret_cast<uint32_t*>(blk + off) = hw;
        *reinterpret_cast<uint32_t*>(blk + 8192 + off) = lw;
    }
}

// ---------------------------------------------------------------------------
// Image GEMM: CTA 128x128, K=1024. 256 threads = 8 warps = 4(M) x 2(N),
// warp tile 32x64. 3-stage cp.async, one barrier per K-tile, fragment
// double-buffering, pass-major issue.
// WMODE 1/2 (proj K/V): bf16 3-pass (hh + hl + lh), 32KB stages.
// WMODE 0  (oproj):     fp16 1-pass (Ah·Bh); HI PLANES ONLY, 16KB stages.
// ---------------------------------------------------------------------------
#define GM_SMEM_BYTES_PROJ (3 * 32768)
#define GM_SMEM_BYTES_OPROJ (3 * 16384)

__device__ __forceinline__ void wr_K_img(int m, int col, float v0, float v1) {
    int s = m & 2047;
    int hb = ((m >> 11) << 4) + (col >> 6);
    int d = col & 63;
    char* blk = (char*)g_KA +
                (size_t)((hb * 16 + (s >> 7)) * 2 + (d >> 5)) * 16384;
    uint32_t off = A16_off(s & 127, (d & 31) >> 1);
    uint32_t hw, lw;
    bf16_split(v0, v1, hw, lw);
    *reinterpret_cast<uint32_t*>(blk + off) = hw;
    *reinterpret_cast<uint32_t*>(blk + 8192 + off) = lw;
}
__device__ __forceinline__ void wr_V_img(int m, int col, float v0, float v1) {
    int s = m & 2047;
    int hb = ((m >> 11) << 4) + (col >> 6);
    int d = col & 63;
    {   // VSB: bf16, n = key (64), k = d (32)
        char* blk = (char*)g_VSB +
                    (size_t)((hb * 32 + (s >> 6)) * 2 + (d >> 5)) * 8192;
        uint32_t off = B16_off64(s & 63, (d & 31) >> 1);
        uint32_t hw, lw;
        bf16_split(v0, v1, hw, lw);
        *reinterpret_cast<uint32_t*>(blk + off) = hw;
        *reinterpret_cast<uint32_t*>(blk + 4096 + off) = lw;
    }
    {   // VPB: fp16 HI ONLY, n = d (64), k = key (32). Adjacent keys live in
        // adjacent g-lanes (lane ^ 4); even-g lanes pack (key s, key s+1).
        float u0 = __shfl_xor_sync(0xffffffffu, v0, 4);
        float u1 = __shfl_xor_sync(0xffffffffu, v1, 4);
        int lane = (int)(threadIdx.x & 31);
        if (!(lane & 4)) {
            char* blk = (char*)g_VPB + (size_t)(hb * 64 + (s >> 5)) * 4096;
            uint32_t p = (uint32_t)((s & 31) >> 1);
            *reinterpret_cast<uint32_t*>(blk + B16_off64(d, p)) =
                f16x2_pack(v0, u0);
            *reinterpret_cast<uint32_t*>(blk + B16_off64(d + 1, p)) =
                f16x2_pack(v1, u1);
        }
    }
}

template <int WMODE>
__device__ void gemm_img_body(const float* __restrict__ Aimg,
                              const float* __restrict__ Bimg,
                              float* __restrict__ Cout) {
    extern __shared__ __align__(1024) char smc[];
    const uint32_t sbase = smem_u32(smc);
    const int tid = threadIdx.x;
    const int lane = tid & 31;
    const int wid = tid >> 5;
    const int warpM = wid & 3;
    const int warpN = wid >> 2;
    const int mb = blockIdx.y;
    const int nb = blockIdx.x;

    constexpr uint32_t STG_SZ = (WMODE == 0) ? 16384u : 32768u;
    constexpr uint32_t B_OFF = (WMODE == 0) ? 8192u : 16384u;

    float c[2][8][4];
#pragma unroll
    for (int i = 0; i < 2; i++)
#pragma unroll
        for (int j = 0; j < 8; j++)
#pragma unroll
            for (int q = 0; q < 4; q++) c[i][j][q] = 0.0f;

    uint32_t ah[2][2][4], al[2][2][4], bh[2][8][2], bl[2][8][2];

    const char* Abase = (const char*)(Aimg) + (size_t)mb * 32 * 16384;
    const char* Bbase = (const char*)(Bimg) + (size_t)nb * 32 * 16384;

    auto issue = [&](int kt) {
        int st = kt % 3;
        if (WMODE == 0) {
            // hi planes only: A-hi 8KB + B-hi 8KB per stage
            if (tid < 128) {
                uint32_t d = sbase + (uint32_t)st * STG_SZ + (uint32_t)tid * 64;
                const char* s = Abase + (size_t)kt * 16384 + tid * 64;
#pragma unroll
                for (int j = 0; j < 4; j++) CP16(d + j * 16, s + j * 16);
            } else {
                uint32_t d = sbase + (uint32_t)st * STG_SZ + B_OFF +
                             (uint32_t)(tid - 128) * 64;
                const char* s = Bbase + (size_t)kt * 16384 + (tid - 128) * 64;
#pragma unroll
                for (int j = 0; j < 4; j++) CP16(d + j * 16, s + j * 16);
            }
        } else {
            if (tid < 128) {
                uint32_t d = sbase + (uint32_t)st * STG_SZ + (uint32_t)tid * 128;
                const char* s = Abase + (size_t)kt * 16384 + tid * 128;
#pragma unroll
                for (int j = 0; j < 8; j++) CP16(d + j * 16, s + j * 16);
            } else {
                uint32_t d = sbase + (uint32_t)st * STG_SZ + B_OFF +
                             (uint32_t)(tid - 128) * 128;
                const char* s = Bbase + (size_t)kt * 16384 + (tid - 128) * 128;
#pragma unroll
                for (int j = 0; j < 8; j++) CP16(d + j * 16, s + j * 16);
            }
        }
        CP_COMMIT();
    };

    auto ldfrag = [&](const char* smb, int kc, int buf) {
#pragma unroll
        for (int tm = 0; tm < 2; tm++) {
            uint32_t off = SW128((uint32_t)(kc * 8 + warpM * 2 + tm) * 512 + lane * 16);
            uint4 h = *reinterpret_cast<const uint4*>(smb + off);
            ah[buf][tm][0] = h.x; ah[buf][tm][1] = h.y;
            ah[buf][tm][2] = h.z; ah[buf][tm][3] = h.w;
            if (WMODE != 0) {
                uint4 l = *reinterpret_cast<const uint4*>(smb + 8192 + off);
                al[buf][tm][0] = l.x; al[buf][tm][1] = l.y;
                al[buf][tm][2] = l.z; al[buf][tm][3] = l.w;
            }
        }
#pragma unroll
        for (int tn = 0; tn < 8; tn++) {
            uint32_t off = SW128((uint32_t)(kc * 16 + warpN * 8 + tn) * 256 + lane * 8);
            uint2 h = *reinterpret_cast<const uint2*>(smb + B_OFF + off);
            bh[buf][tn][0] = h.x; bh[buf][tn][1] = h.y;
            if (WMODE != 0) {
                uint2 l = *reinterpret_cast<const uint2*>(smb + B_OFF + 8192 + off);
                bl[buf][tn][0] = l.x; bl[buf][tn][1] = l.y;
            }
        }
    };

    issue(0);
    issue(1);
    for (int kt = 0; kt < 32; kt++) {
        if (kt < 31) CP_WAIT(1); else CP_WAIT(0);
        __syncthreads();
        if (kt + 2 < 32) issue(kt + 2);
        const char* smb = smc + (uint32_t)(kt % 3) * STG_SZ;

        ldfrag(smb, 0, 0);
#pragma unroll
        for (int kc = 0; kc < 2; kc++) {
            const int cur = kc & 1;
            if (kc < 1) ldfrag(smb, kc + 1, cur ^ 1);
            if (WMODE == 0) {
                // fp16 1-pass: Ah·Bh
#pragma unroll
                for (int tm = 0; tm < 2; tm++)
#pragma unroll
                    for (int tn = 0; tn < 8; tn++)
                        mma_f16(c[tm][tn], ah[cur][tm], bh[cur][tn]);
            } else {
                // bf16 3-pass: Ah·Bh + Ah·Bl + Al·Bh
#pragma unroll
                for (int tm = 0; tm < 2; tm++)
#pragma unroll
                    for (int tn = 0; tn < 8; tn++)
                        mma_bf16(c[tm][tn], ah[cur][tm], bh[cur][tn]);
#pragma unroll
                for (int tm = 0; tm < 2; tm++)
#pragma unroll
                    for (int tn = 0; tn < 8; tn++)
                        mma_bf16(c[tm][tn], ah[cur][tm], bl[cur][tn]);
#pragma unroll
                for (int tm = 0; tm < 2; tm++)
#pragma unroll
                    for (int tn = 0; tn < 8; tn++)
                        mma_bf16(c[tm][tn], al[cur][tm], bh[cur][tn]);
            }
        }
    }

    const int g = lane >> 2;
    const int t4 = lane & 3;
    const int bm = mb * 128;
    const int bn = nb * 128;
#pragma unroll
    for (int tm = 0; tm < 2; tm++) {
#pragma unroll
        for (int tn = 0; tn < 8; tn++) {
            int row0 = bm + warpM * 32 + tm * 16 + g;
            int col = bn + warpN * 64 + tn * 8 + t4 * 2;
#pragma unroll
            for (int hrow = 0; hrow < 2; hrow++) {
                int m = row0 + hrow * 8;
                float v0 = c[tm][tn][2 * hrow];
                float v1 = c[tm][tn][2 * hrow + 1];
                if (WMODE == 1) {
                    wr_K_img(m, col, v0, v1);
                } else if (WMODE == 2) {
                    wr_V_img(m, col, v0, v1);
                } else {
                    *reinterpret_cast<float2*>(Cout + (size_t)m * 1024 + col) =
                        make_float2(v0, v1);
                }
            }
        }
    }
}

__global__ __launch_bounds__(256, 1) void proj_img_kernel() {
    if (blockIdx.z == 0)
        gemm_img_body<1>(g_xA, g_WkB, nullptr);
    else
        gemm_img_body<2>(g_xA, g_WvB, nullptr);
}
__global__ __launch_bounds__(256, 1) void oproj_img_kernel(float* __restrict__ out) {
    gemm_img_body<0>(g_OA, g_WoB, out);
}

// ---------------------------------------------------------------------------
// Tensor-core attention:
//   S = K·V^T in 3x-bf16 (k16); softmax; O += P_fp16 · V_fp16hi (1 pass).
// l sums the SAME fp16-quantized p values the MMA consumes (common-mode
// quantization absorbed); V_lo drop costs ~2^-11 relative on O.
// Per (b,h), q-block of 128 rows (CTA), key-tiles of 64. 256 thr = 8 warps;
// warp w owns rows w*16..w*16+15.
// SMEM: K bf16 images 32KB | P fp16 image 16KB | 2 stages x (VSB 16KB + VPB 8KB)
// ---------------------------------------------------------------------------
#define ATT_K 0
#define ATT_P 32768
#define ATT_STG 49152
#define ATT_STAGE_SZ 24576
#define ATT_SMEM_BYTES (49152 + 2 * ATT_STAGE_SZ)

__global__ __launch_bounds__(256, 1) void attn_mma_kernel() {
    extern __shared__ __align__(1024) char smc[];
    const uint32_t sbase = smem_u32(smc);
    const int tid = threadIdx.x;
    const int lane = tid & 31;
    const int w = tid >> 5;
    const int g = lane >> 2;
    const int t4 = lane & 3;
    const int hb = blockIdx.y;
    const int mb = blockIdx.x;
    const float SC = -32.0f * 1.4426950408889634f;

    const char* KAg = (const char*)g_KA + (size_t)(hb * 16 + mb) * 32768;
    const char* VSBg = (const char*)g_VSB + (size_t)hb * 32 * 16384;
    const char* VPBg = (const char*)g_VPB + (size_t)hb * 64 * 4096;

    auto issue_stage = [&](int i) {
        uint32_t stg = (uint32_t)(ATT_STG + (i & 1) * ATT_STAGE_SZ);
        if (tid < 128) {
            uint32_t d = sbase + stg + (uint32_t)tid * 128;
            const char* s = VSBg + (size_t)i * 16384 + tid * 128;
#pragma unroll
            for (int j = 0; j < 8; j++) CP16(d + j * 16, s + j * 16);
        } else {
            uint32_t d = sbase + stg + 16384 + (uint32_t)(tid - 128) * 64;
            const char* s = VPBg + (size_t)(2 * i) * 4096 + (tid - 128) * 64;
#pragma unroll
            for (int j = 0; j < 4; j++) CP16(d + j * 16, s + j * 16);
        }
        CP_COMMIT();
    };

    // Prologue: K (32KB, joins group 0) + stage0, then stage1
    {
        uint32_t d = sbase + (uint32_t)tid * 128;
        const char* s = KAg + tid * 128;
#pragma unroll
        for (int j = 0; j < 8; j++) CP16(d + j * 16, s + j * 16);
    }
    issue_stage(0);
    issue_stage(1);

    float o[8][4];
#pragma unroll
    for (int tn = 0; tn < 8; tn++)
#pragma unroll
        for (int q = 0; q < 4; q++) o[tn][q] = 0.0f;
    float m0 = -INFINITY, m1 = -INFINITY, l0 = 0.0f, l1 = 0.0f;

    for (int i = 0; i < 32; i++) {
        if (i < 31) CP_WAIT(1); else CP_WAIT(0);
        __syncthreads();
        const uint32_t stg = (uint32_t)(ATT_STG + (i & 1) * ATT_STAGE_SZ);

        // ---- S = K·V^T (128 x 64), 3x-bf16, frag double-buffer, pass-major ----
        float s[8][4];
#pragma unroll
        for (int tn = 0; tn < 8; tn++)
#pragma unroll
            for (int q = 0; q < 4; q++) s[tn][q] = 0.0f;

        uint32_t ah[2][4], al[2][4], bh[2][8][2], bl[2][8][2];
        auto ld_s_frag = [&](int kc, int buf) {
            int dc = kc >> 1;   // which 32-d chunk (16KB block)
            int kci = kc & 1;   // k16 chunk within block
            uint32_t aoff = (uint32_t)(ATT_K + dc * 16384) +
                            SW128((uint32_t)(kci * 8 + w) * 512 + lane * 16);
            uint4 h4 = *reinterpret_cast<const uint4*>(smc + aoff);
            uint4 l4 = *reinterpret_cast<const uint4*>(smc + aoff + 8192);
            ah[buf][0] = h4.x; ah[buf][1] = h4.y; ah[buf][2] = h4.z; ah[buf][3] = h4.w;
            al[buf][0] = l4.x; al[buf][1] = l4.y; al[buf][2] = l4.z; al[buf][3] = l4.w;
#pragma unroll
            for (int tn = 0; tn < 8; tn++) {
                uint32_t boff = stg + (uint32_t)(dc * 8192) +
                                SW128((uint32_t)(kci * 8 + tn) * 256 + lane * 8);
                uint2 bh2 = *reinterpret_cast<const uint2*>(smc + boff);
                uint2 bl2 = *reinterpret_cast<const uint2*>(smc + boff + 4096);
                bh[buf][tn][0] = bh2.x; bh[buf][tn][1] = bh2.y;
                bl[buf][tn][0] = bl2.x; bl[buf][tn][1] = bl2.y;
            }
        };

        ld_s_frag(0, 0);
#pragma unroll
        for (int kc = 0; kc < 4; kc++) {
            const int cur = kc & 1;
            if (kc < 3) ld_s_frag(kc + 1, cur ^ 1);
#pragma unroll
            for (int tn = 0; tn < 8; tn++) mma_bf16(s[tn], ah[cur], bh[cur][tn]);
#pragma unroll
            for (int tn = 0; tn < 8; tn++) mma_bf16(s[tn], ah[cur], bl[cur][tn]);
#pragma unroll
            for (int tn = 0; tn < 8; tn++) mma_bf16(s[tn], al[cur], bh[cur][tn]);
        }

        // ---- softmax over this 64-key tile (rows: w*16+g, w*16+g+8) ----
#pragma unroll
        for (int tn = 0; tn < 8; tn++)
#pragma unroll
            for (int q = 0; q < 4; q++) s[tn][q] *= SC;

        float mx0 = s[0][0], mx1 = s[0][2];
#pragma unroll
        for (int tn = 0; tn < 8; tn++) {
            mx0 = fmaxf(mx0, fmaxf(s[tn][0], s[tn][1]));
            mx1 = fmaxf(mx1, fmaxf(s[tn][2], s[tn][3]));
        }
        mx0 = fmaxf(mx0, __shfl_xor_sync(0xffffffffu, mx0, 1));
        mx0 = fmaxf(mx0, __shfl_xor_sync(0xffffffffu, mx0, 2));
        mx1 = fmaxf(mx1, __shfl_xor_sync(0xffffffffu, mx1, 1));
        mx1 = fmaxf(mx1, __shfl_xor_sync(0xffffffffu, mx1, 2));

        float mn0 = fmaxf(m0, mx0), mn1 = fmaxf(m1, mx1);
        float al0 = fast_exp2(m0 - mn0), al1 = fast_exp2(m1 - mn1);
        m0 = mn0; m1 = mn1;

        // Quantize p to fp16 (the exact values the PV MMA consumes), pack two
        // adjacent keys per thread into one fp16x2 P-image word, sum quantized
        // values into l.
        float rs0 = 0.0f, rs1 = 0.0f;
        const int r0 = w * 16 + g;
#pragma unroll
        for (int tn = 0; tn < 8; tn++) {
            int pairIdx = tn * 4 + t4;  // 0..31 (keys 2*pairIdx, 2*pairIdx+1)
#pragma unroll
            for (int hrow = 0; hrow < 2; hrow++) {
                float mnv = hrow ? mn1 : mn0;
                float p0 = fast_exp2(s[tn][2 * hrow] - mnv);
                float p1 = fast_exp2(s[tn][2 * hrow + 1] - mnv);
                __half2 ph = __floats2half2_rn(p0, p1);
                uint32_t pw = *reinterpret_cast<uint32_t*>(&ph);
                float pq0 = __low2float(ph);
                float pq1 = __high2float(ph);
                if (hrow) rs1 += pq0 + pq1; else rs0 += pq0 + pq1;
                int row = r0 + hrow * 8;
                *reinterpret_cast<uint32_t*>(
                    smc + ATT_P + (pairIdx >> 4) * 8192 +
                    A16_off(row, pairIdx & 15)) = pw;
            }
        }
        rs0 += __shfl_xor_sync(0xffffffffu, rs0, 1);
        rs0 += __shfl_xor_sync(0xffffffffu, rs0, 2);
        rs1 += __shfl_xor_sync(0xffffffffu, rs1, 1);
        rs1 += __shfl_xor_sync(0xffffffffu, rs1, 2);
        l0 = l0 * al0 + rs0;
        l1 = l1 * al1 + rs1;
#pragma unroll
        for (int tn = 0; tn < 8; tn++) {
            o[tn][0] *= al0; o[tn][1] *= al0;
            o[tn][2] *= al1; o[tn][3] *= al1;
        }
        __syncwarp();

        // ---- O += P_fp16 · V_fp16hi (single pass), frag double-buffer ----
        uint32_t pa[2][4], vh[2][8][2];
        auto ld_pv_frag = [&](int kk, int buf) {   // kk = k16 step, 0..3
            int kc = kk >> 1;   // 32-key chunk
            int kci = kk & 1;   // k16 within chunk
            uint32_t poff = (uint32_t)(ATT_P + kc * 8192) +
                            SW128((uint32_t)(kci * 8 + w) * 512 + lane * 16);
            uint4 p4 = *reinterpret_cast<const uint4*>(smc + poff);
            pa[buf][0] = p4.x; pa[buf][1] = p4.y; pa[buf][2] = p4.z; pa[buf][3] = p4.w;
#pragma unroll
            for (int tn = 0; tn < 8; tn++) {
                uint32_t voff = stg + (uint32_t)(16384 + kc * 4096) +
                                SW128((uint32_t)(kci * 8 + tn) * 256 + lane * 8);
                uint2 vh2 = *reinterpret_cast<const uint2*>(smc + voff);
                vh[buf][tn][0] = vh2.x; vh[buf][tn][1] = vh2.y;
            }
        };

        ld_pv_frag(0, 0);
#pragma unroll
        for (int kk = 0; kk < 4; kk++) {
            const int cur = kk & 1;
            if (kk < 3) ld_pv_frag(kk + 1, cur ^ 1);
#pragma unroll
            for (int tn = 0; tn < 8; tn++) mma_f16(o[tn], pa[cur], vh[cur][tn]);
        }
        __syncthreads();
        if (i < 30) issue_stage(i + 2);
    }

    // ---- epilogue: normalize and write g_OA fp16 A-images (HI plane only;
    // the 1-pass oproj never reads the lo plane) ----
    const int b = hb >> 4;
    const int h = hb & 15;
    const float inv0 = 1.0f / l0, inv1 = 1.0f / l1;
    const int rbase = b * 2048 + mb * 128 + w * 16 + g;
#pragma unroll
    for (int tn = 0; tn < 8; tn++) {
        int d0 = h * 64 + tn * 8 + t4 * 2;
#pragma unroll
        for (int hrow = 0; hrow < 2; hrow++) {
            int row = rbase + hrow * 8;
            float inv = hrow ? inv1 : inv0;
            float v0 = o[tn][2 * hrow] * inv;
            float v1 = o[tn][2 * hrow + 1] * inv;
            char* blk = (char*)g_OA + (size_t)((row >> 7) * 32 + (d0 >> 5)) * 16384;
            uint32_t off = A16_off(row & 127, (d0 & 31) >> 1);
            *reinterpret_cast<uint32_t*>(blk + off) = f16x2_pack(v0, v1);
        }
    }
}

extern "C" void kernel_launch(void* const* d_in, const int* in_sizes, int n_in,
                              void* d_out, int out_size) {
    const float* x = (const float*)d_in[0];
    // d_in[1] = Wq (dead code in the reference dataflow)
    const float* Wk = (const float*)d_in[2];
    const float* Wv = (const float*)d_in[3];
    const float* Wo = (const float*)d_in[4];
    float* out = (float*)d_out;

    cudaFuncSetAttribute(proj_img_kernel, cudaFuncAttributeMaxDynamicSharedMemorySize,
                         GM_SMEM_BYTES_PROJ);
    cudaFuncSetAttribute(oproj_img_kernel, cudaFuncAttributeMaxDynamicSharedMemorySize,
                         GM_SMEM_BYTES_OPROJ);
    cudaFuncSetAttribute(attn_mma_kernel, cudaFuncAttributeMaxDynamicSharedMemorySize,
                         ATT_SMEM_BYTES);

    // 1) Pre-split inputs into fragment images (x/Wk/Wv bf16, Wo fp16)
    split_kernel<<<dim3(32, 32, 4), 128>>>(x, Wk, Wv, Wo);

    // 2) K/V projections (3x-bf16); epilogues write K/V attention images
    proj_img_kernel<<<dim3(8, 32, 2), 256, GM_SMEM_BYTES_PROJ>>>();

    // 3) Tensor-core attention (S: 3x-bf16, PV: 1x-fp16), writes g_OA hi images
    attn_mma_kernel<<<dim3(16, 32), 256, ATT_SMEM_BYTES>>>();

    // 4) Output projection (1x-fp16, hi planes only)
    oproj_img_kernel<<<dim3(8, 32), 256, GM_SMEM_BYTES_OPROJ>>>(out);
}